// round 15
// baseline (speedup 1.0000x reference)
#include <cuda_runtime.h>
#include <cuda_bf16.h>
#include <mma.h>
#include <math.h>
#include <stdint.h>

using namespace nvcuda;

#define Nn 10000
#define Ee 128000

// ---------------- scratch (device globals: allocation-free) ----------------
__device__ float g_h[(size_t)Nn * 512];   // [n][0:128]=h0, [128+k*128+u]=h1[u,k]
__device__ float g_M[(size_t)Nn * 1024];  // [n][j*256 + c] j=0:M0, j>0:M1[:,j-1]
__device__ float g_dens[Nn];

// pre-converted weights (bf16 hi/lo), chunk-major for conflict-free staging
__device__ __nv_bfloat16 g_BupH[2][2][128][64];   // [sel][chunk][v][kk]
__device__ __nv_bfloat16 g_BupL[2][2][128][64];
__device__ __nv_bfloat16 g_BskH[2][20][128][64];  // K reordered: k = a*128+u
__device__ __nv_bfloat16 g_BskL[2][20][128][64];
__device__ __nv_bfloat16 g_BlnH[2][4][128][64];   // W_lin: [sel][chunk][v][kk]
__device__ __nv_bfloat16 g_BlnL[2][4][128][64];

// ---------------- streams/events for graph fork (created pre-main) --------
static cudaStream_t g_s2;
static cudaEvent_t g_evF, g_evP, g_evB;
namespace {
struct StreamInit {
    StreamInit() {
        int lo = 0, hi = 0;
        cudaDeviceGetStreamPriorityRange(&lo, &hi);  // lo = least priority
        cudaStreamCreateWithPriority(&g_s2, cudaStreamNonBlocking, lo);
        cudaEventCreateWithFlags(&g_evF, cudaEventDisableTiming);
        cudaEventCreateWithFlags(&g_evP, cudaEventDisableTiming);
        cudaEventCreateWithFlags(&g_evB, cudaEventDisableTiming);
    }
};
StreamInit g_stream_init;
}

// 16B vector reduction (sm_90+)
#define RED4(p, va, vb, vc, vd)                                         \
    asm volatile("red.global.add.v4.f32 [%0], {%1, %2, %3, %4};"        \
                 :: "l"(p), "f"(va), "f"(vb), "f"(vc), "f"(vd) : "memory")

__device__ __forceinline__ void bf16_split(float v, __nv_bfloat16& h, __nv_bfloat16& l) {
    h = __float2bfloat16(v);
    l = __float2bfloat16(v - __bfloat162float(h));
}

// ---------------- prep (main): Bup conversion + accumulator clears --------
__global__ void prep_main_kernel(const float* __restrict__ Wup0,
                                 const float* __restrict__ Wup1) {
    int stride = gridDim.x * blockDim.x;
    int i = blockIdx.x * blockDim.x + threadIdx.x;
    for (int p = i; p < 32768; p += stride) {
        int kk = p & 63, v = (p >> 6) & 127, c = (p >> 13) & 1, sel = p >> 14;
        const float* W = sel ? Wup1 : Wup0;
        float val = W[(c * 64 + kk) * 128 + v];
        __nv_bfloat16 h, l; bf16_split(val, h, l);
        g_BupH[sel][c][v][kk] = h;
        g_BupL[sel][c][v][kk] = l;
    }
    float4 z = make_float4(0.f, 0.f, 0.f, 0.f);
    for (int p = i; p < Nn * 1024 / 4; p += stride) ((float4*)g_M)[p] = z;
    for (int p = i; p < Nn; p += stride) g_dens[p] = 0.f;
}

// ---------------- prep (side): Bsk + Bln conversions -----------------------
__global__ void prep_side_kernel(const float* __restrict__ Wsk0,
                                 const float* __restrict__ Wsk1,
                                 const float* __restrict__ Wl0,
                                 const float* __restrict__ Wl1) {
    int stride = gridDim.x * blockDim.x;
    int i = blockIdx.x * blockDim.x + threadIdx.x;
    for (int p = i; p < 327680; p += stride) {
        int sel = p >= 163840;
        int q = p - sel * 163840;
        int kk = q & 63, v = (q >> 6) & 127, c = q >> 13;  // c in 0..19
        int a = c >> 1, u = (c & 1) * 64 + kk;
        const float* W = sel ? Wsk1 : Wsk0;
        float val = W[u * 1280 + a * 128 + v];
        __nv_bfloat16 h, l; bf16_split(val, h, l);
        g_BskH[sel][c][v][kk] = h;
        g_BskL[sel][c][v][kk] = l;
    }
    for (int p = i; p < 65536; p += stride) {
        int kk = p & 63, v = (p >> 6) & 127, c = (p >> 13) & 3, sel = p >> 15;
        const float* W = sel ? Wl1 : Wl0;
        float val = W[(c * 64 + kk) * 128 + v];
        __nv_bfloat16 h, l; bf16_split(val, h, l);
        g_BlnH[sel][c][v][kk] = h;
        g_BlnL[sel][c][v][kk] = l;
    }
}

#define LDT 72
#define TILE_BYTES 73728
#define NK_SM_TOTAL 219136        // xs 65536 + ats 6144 + 2*73728

// ---------------- stage xs helper ------------------------------------------
__device__ __forceinline__ void stage_xs(float* xs, const float* __restrict__ nf,
                                         int j, int nb, int tid, int nthr) {
    if (j == 0) {
        for (int p = tid; p < 4096; p += nthr) {
            int n = p >> 5, u4 = (p & 31) << 2;
            int gn = nb + n;
            float4 v = make_float4(0.f, 0.f, 0.f, 0.f);
            if (gn < Nn) v = *(const float4*)(nf + (size_t)gn * 512 + u4);
            *(float4*)(xs + n * 128 + u4) = v;
        }
    } else {
        int kc2 = j - 1;
        for (int p = tid; p < 16384; p += nthr) {
            int n = p >> 7, u = p & 127;
            int gn = nb + n;
            xs[p] = (gn < Nn) ? nf[(size_t)gn * 512 + 128 + u * 3 + kc2] : 0.f;
        }
    }
}

// ---------------- node UP kernel: h = x @ Wup / sqrt(128) ------------------
__global__ __launch_bounds__(1024) void node_up_kernel(
        const float* __restrict__ nf) {
    extern __shared__ char smc[];
    float* xs = (float*)smc;
    char* tiles = smc + 71680;
    float* Dov = (float*)(smc + 71680);

    const int tid = threadIdx.x;
    const int wid = tid >> 5;
    const int j = blockIdx.y;
    const int nb = blockIdx.x * 128;
    const int m0 = (wid & 7) * 16;
    const int nq = wid >> 3;
    const int sel = (j == 0) ? 0 : 1;

    stage_xs(xs, nf, j, nb, tid, 1024);
    __syncthreads();

    int tn[2], tk[2];
#pragma unroll
    for (int i = 0; i < 2; i++) {
        int p = tid + i * 1024;
        tn[i] = p >> 4;
        tk[i] = (p & 15) << 2;
    }

    wmma::fragment<wmma::accumulator, 16, 16, 16, float> facc[2];
    wmma::fragment<wmma::matrix_a, 16, 16, 16, __nv_bfloat16, wmma::row_major> fah, fal;
    wmma::fragment<wmma::matrix_b, 16, 16, 16, __nv_bfloat16, wmma::col_major> fbh, fbl;
#pragma unroll
    for (int t = 0; t < 2; t++) wmma::fill_fragment(facc[t], 0.f);

    float4 a4[2];
    uint2 bhp[2], blp[2];

    {
#pragma unroll
        for (int i = 0; i < 2; i++) {
            a4[i] = *(float4*)(xs + tn[i] * 128 + tk[i]);
            bhp[i] = *(const uint2*)&g_BupH[sel][0][tn[i]][tk[i]];
            blp[i] = *(const uint2*)&g_BupL[sel][0][tn[i]][tk[i]];
        }
        __nv_bfloat16* Ahi = (__nv_bfloat16*)tiles;
        __nv_bfloat16* Alo = (__nv_bfloat16*)(tiles + 18432);
        __nv_bfloat16* Bhi = (__nv_bfloat16*)(tiles + 36864);
        __nv_bfloat16* Blo = (__nv_bfloat16*)(tiles + 55296);
#pragma unroll
        for (int i = 0; i < 2; i++) {
            int o = tn[i] * LDT + tk[i];
            __nv_bfloat16 h0, h1, h2, h3, l0, l1, l2, l3;
            bf16_split(a4[i].x, h0, l0); bf16_split(a4[i].y, h1, l1);
            bf16_split(a4[i].z, h2, l2); bf16_split(a4[i].w, h3, l3);
            Ahi[o] = h0; Ahi[o + 1] = h1; Ahi[o + 2] = h2; Ahi[o + 3] = h3;
            Alo[o] = l0; Alo[o + 1] = l1; Alo[o + 2] = l2; Alo[o + 3] = l3;
            *(uint2*)&Bhi[o] = bhp[i];
            *(uint2*)&Blo[o] = blp[i];
        }
    }
    __syncthreads();

    for (int c = 0; c < 2; c++) {
        const bool more = (c + 1) < 2;
        if (more) {
#pragma unroll
            for (int i = 0; i < 2; i++) {
                a4[i] = *(float4*)(xs + tn[i] * 128 + 64 + tk[i]);
                bhp[i] = *(const uint2*)&g_BupH[sel][1][tn[i]][tk[i]];
                blp[i] = *(const uint2*)&g_BupL[sel][1][tn[i]][tk[i]];
            }
        }
        {
            char* tb = tiles + (c & 1) * TILE_BYTES;
            __nv_bfloat16* Ahi = (__nv_bfloat16*)tb;
            __nv_bfloat16* Alo = (__nv_bfloat16*)(tb + 18432);
            __nv_bfloat16* Bhi = (__nv_bfloat16*)(tb + 36864);
            __nv_bfloat16* Blo = (__nv_bfloat16*)(tb + 55296);
#pragma unroll
            for (int kk = 0; kk < 4; kk++) {
                wmma::load_matrix_sync(fah, Ahi + m0 * LDT + kk * 16, LDT);
                wmma::load_matrix_sync(fal, Alo + m0 * LDT + kk * 16, LDT);
#pragma unroll
                for (int t = 0; t < 2; t++) {
                    int nt = nq * 2 + t;
                    wmma::load_matrix_sync(fbh, Bhi + nt * 16 * LDT + kk * 16, LDT);
                    wmma::load_matrix_sync(fbl, Blo + nt * 16 * LDT + kk * 16, LDT);
                    wmma::mma_sync(facc[t], fah, fbh, facc[t]);
                    wmma::mma_sync(facc[t], fah, fbl, facc[t]);
                    wmma::mma_sync(facc[t], fal, fbh, facc[t]);
                }
            }
        }
        if (more) {
            char* tb = tiles + ((c + 1) & 1) * TILE_BYTES;
            __nv_bfloat16* Ahi = (__nv_bfloat16*)tb;
            __nv_bfloat16* Alo = (__nv_bfloat16*)(tb + 18432);
            __nv_bfloat16* Bhi = (__nv_bfloat16*)(tb + 36864);
            __nv_bfloat16* Blo = (__nv_bfloat16*)(tb + 55296);
#pragma unroll
            for (int i = 0; i < 2; i++) {
                int o = tn[i] * LDT + tk[i];
                __nv_bfloat16 h0, h1, h2, h3, l0, l1, l2, l3;
                bf16_split(a4[i].x, h0, l0); bf16_split(a4[i].y, h1, l1);
                bf16_split(a4[i].z, h2, l2); bf16_split(a4[i].w, h3, l3);
                Ahi[o] = h0; Ahi[o + 1] = h1; Ahi[o + 2] = h2; Ahi[o + 3] = h3;
                Alo[o] = l0; Alo[o + 1] = l1; Alo[o + 2] = l2; Alo[o + 3] = l3;
                *(uint2*)&Bhi[o] = bhp[i];
                *(uint2*)&Blo[o] = blp[i];
            }
        }
        __syncthreads();
    }

#pragma unroll
    for (int t = 0; t < 2; t++)
        wmma::store_matrix_sync(Dov + m0 * 128 + nq * 32 + t * 16, facc[t], 128,
                                wmma::mem_row_major);
    __syncthreads();

    const float sh = 0.08838834764831845f;  // 1/sqrt(128)
    for (int p = tid; p < 4096; p += 1024) {
        int n = p >> 5, v4 = (p & 31) << 2;
        int gn = nb + n;
        if (gn < Nn) {
            float4 d = *(float4*)(Dov + n * 128 + v4);
            float4 o = make_float4(d.x * sh, d.y * sh, d.z * sh, d.w * sh);
            *(float4*)(g_h + (size_t)gn * 512 + j * 128 + v4) = o;
        }
    }
}

// ---------------- node SKIP kernel (independent of up/edge/lin) -------------
__global__ __launch_bounds__(1024) void node_skip_kernel(
        const float* __restrict__ nf, const float* __restrict__ na,
        float* __restrict__ sc_out) {
    extern __shared__ char smc[];
    float* xs  = (float*)smc;
    float* ats = (float*)(smc + 65536);
    char*  tiles = smc + 71680;
    float* Dov = (float*)(smc + 71680);

    const int tid = threadIdx.x;
    const int wid = tid >> 5;
    const int j = blockIdx.y;
    const int nb = blockIdx.x * 128;
    const int m0 = (wid & 7) * 16;
    const int nq = wid >> 3;
    const int sel = (j == 0) ? 0 : 1;

    stage_xs(xs, nf, j, nb, tid, 1024);
    for (int p = tid; p < 1280; p += 1024) {
        int n = p / 10, a = p - n * 10;
        int gn = nb + n;
        ats[n * 12 + a] = (gn < Nn) ? na[(size_t)gn * 10 + a] : 0.f;
    }
    __syncthreads();

    int tn[2], tk[2];
#pragma unroll
    for (int i = 0; i < 2; i++) {
        int p = tid + i * 1024;
        tn[i] = p >> 4;
        tk[i] = (p & 15) << 2;
    }

    wmma::fragment<wmma::accumulator, 16, 16, 16, float> facc[2];
    wmma::fragment<wmma::matrix_a, 16, 16, 16, __nv_bfloat16, wmma::row_major> fah, fal;
    wmma::fragment<wmma::matrix_b, 16, 16, 16, __nv_bfloat16, wmma::col_major> fbh, fbl;
#pragma unroll
    for (int t = 0; t < 2; t++) wmma::fill_fragment(facc[t], 0.f);

    float4 a4[2];
    float  atv[2];
    uint2  bhp[2], blp[2];

    {
#pragma unroll
        for (int i = 0; i < 2; i++) {
            a4[i] = *(float4*)(xs + tn[i] * 128 + tk[i]);
            atv[i] = ats[tn[i] * 12 + 0];
            bhp[i] = *(const uint2*)&g_BskH[sel][0][tn[i]][tk[i]];
            blp[i] = *(const uint2*)&g_BskL[sel][0][tn[i]][tk[i]];
        }
        __nv_bfloat16* Ahi = (__nv_bfloat16*)tiles;
        __nv_bfloat16* Alo = (__nv_bfloat16*)(tiles + 18432);
        __nv_bfloat16* Bhi = (__nv_bfloat16*)(tiles + 36864);
        __nv_bfloat16* Blo = (__nv_bfloat16*)(tiles + 55296);
#pragma unroll
        for (int i = 0; i < 2; i++) {
            int o = tn[i] * LDT + tk[i];
            __nv_bfloat16 h0, h1, h2, h3, l0, l1, l2, l3;
            bf16_split(a4[i].x * atv[i], h0, l0);
            bf16_split(a4[i].y * atv[i], h1, l1);
            bf16_split(a4[i].z * atv[i], h2, l2);
            bf16_split(a4[i].w * atv[i], h3, l3);
            Ahi[o] = h0; Ahi[o + 1] = h1; Ahi[o + 2] = h2; Ahi[o + 3] = h3;
            Alo[o] = l0; Alo[o + 1] = l1; Alo[o + 2] = l2; Alo[o + 3] = l3;
            *(uint2*)&Bhi[o] = bhp[i];
            *(uint2*)&Blo[o] = blp[i];
        }
    }
    __syncthreads();

    for (int c = 0; c < 20; c++) {
        const bool more = (c + 1) < 20;
        if (more) {
            const int cn = c + 1;
            const int xcol = (cn & 1) * 64;
            const int an = cn >> 1;
#pragma unroll
            for (int i = 0; i < 2; i++) {
                a4[i] = *(float4*)(xs + tn[i] * 128 + xcol + tk[i]);
                atv[i] = ats[tn[i] * 12 + an];
                bhp[i] = *(const uint2*)&g_BskH[sel][cn][tn[i]][tk[i]];
                blp[i] = *(const uint2*)&g_BskL[sel][cn][tn[i]][tk[i]];
            }
        }
        {
            char* tb = tiles + (c & 1) * TILE_BYTES;
            __nv_bfloat16* Ahi = (__nv_bfloat16*)tb;
            __nv_bfloat16* Alo = (__nv_bfloat16*)(tb + 18432);
            __nv_bfloat16* Bhi = (__nv_bfloat16*)(tb + 36864);
            __nv_bfloat16* Blo = (__nv_bfloat16*)(tb + 55296);
#pragma unroll
            for (int kk = 0; kk < 4; kk++) {
                wmma::load_matrix_sync(fah, Ahi + m0 * LDT + kk * 16, LDT);
                wmma::load_matrix_sync(fal, Alo + m0 * LDT + kk * 16, LDT);
#pragma unroll
                for (int t = 0; t < 2; t++) {
                    int nt = nq * 2 + t;
                    wmma::load_matrix_sync(fbh, Bhi + nt * 16 * LDT + kk * 16, LDT);
                    wmma::load_matrix_sync(fbl, Blo + nt * 16 * LDT + kk * 16, LDT);
                    wmma::mma_sync(facc[t], fah, fbh, facc[t]);
                    wmma::mma_sync(facc[t], fah, fbl, facc[t]);
                    wmma::mma_sync(facc[t], fal, fbh, facc[t]);
                }
            }
        }
        if (more) {
            char* tb = tiles + ((c + 1) & 1) * TILE_BYTES;
            __nv_bfloat16* Ahi = (__nv_bfloat16*)tb;
            __nv_bfloat16* Alo = (__nv_bfloat16*)(tb + 18432);
            __nv_bfloat16* Bhi = (__nv_bfloat16*)(tb + 36864);
            __nv_bfloat16* Blo = (__nv_bfloat16*)(tb + 55296);
#pragma unroll
            for (int i = 0; i < 2; i++) {
                int o = tn[i] * LDT + tk[i];
                __nv_bfloat16 h0, h1, h2, h3, l0, l1, l2, l3;
                bf16_split(a4[i].x * atv[i], h0, l0);
                bf16_split(a4[i].y * atv[i], h1, l1);
                bf16_split(a4[i].z * atv[i], h2, l2);
                bf16_split(a4[i].w * atv[i], h3, l3);
                Ahi[o] = h0; Ahi[o + 1] = h1; Ahi[o + 2] = h2; Ahi[o + 3] = h3;
                Alo[o] = l0; Alo[o + 1] = l1; Alo[o + 2] = l2; Alo[o + 3] = l3;
                *(uint2*)&Bhi[o] = bhp[i];
                *(uint2*)&Blo[o] = blp[i];
            }
        }
        __syncthreads();
    }

#pragma unroll
    for (int t = 0; t < 2; t++)
        wmma::store_matrix_sync(Dov + m0 * 128 + nq * 32 + t * 16, facc[t], 128,
                                wmma::mem_row_major);
    __syncthreads();

    const float ss = 0.027950849718747373f;  // 1/sqrt(1280)
    if (j == 0) {
        for (int p = tid; p < 4096; p += 1024) {
            int n = p >> 5, v4 = (p & 31) << 2;
            int gn = nb + n;
            if (gn < Nn) {
                float4 d = *(float4*)(Dov + n * 128 + v4);
                float4 o = make_float4(d.x * ss, d.y * ss, d.z * ss, d.w * ss);
                *(float4*)(sc_out + (size_t)gn * 512 + v4) = o;
            }
        }
    } else {
        for (int p = tid; p < 16384; p += 1024) {
            int n = p >> 7, v = p & 127;
            int gn = nb + n;
            if (gn < Nn)
                sc_out[(size_t)gn * 512 + 128 + v * 3 + (j - 1)] =
                    Dov[n * 128 + v] * ss;
        }
    }
}

// ---------------- fused edge kernel: 64 edges/block, 3 blocks/SM -----------
// smem layout (floats): ef 512 | r0 512 | y 256 | si 64 | ri 64 |
//   At_a 64x68=4352 | At_b 4352 | s_B 8192  => 18304 floats = 73216 B
#define EG_SM_TOTAL 73216
__global__ __launch_bounds__(512, 3) void edge_kernel(
        const float* __restrict__ ef, const float* __restrict__ ea,
        const int* __restrict__ eidx, const float* __restrict__ Wd,
        const float* __restrict__ R0, const float* __restrict__ R1,
        const float* __restrict__ R2, const float* __restrict__ R3) {
    extern __shared__ float sm[];
    float* s_ef = sm;                 // 512 (64*8)
    float* s_r0 = sm + 512;           // 512
    float* s_y  = sm + 1024;          // 256
    int*   s_si = (int*)(sm + 1280);  // 64
    int*   s_ri = (int*)(sm + 1344);  // 64
    float* At_a = sm + 1408;          // 64x68 = 4352
    float* At_b = At_a + 4352;        // 4352
    float* s_B  = At_b + 4352;        // 8192

    const int tid = threadIdx.x;
    const int eb = blockIdx.x * 64;

    for (int p = tid; p < 128; p += 512)
        ((float4*)s_ef)[p] = ((const float4*)(ef + (size_t)eb * 8))[p];
    for (int p = tid; p < 64; p += 512)
        ((float4*)s_y)[p] = ((const float4*)(ea + (size_t)eb * 4))[p];
    if (tid < 64) {
        s_si[tid] = eidx[eb + tid];
        s_ri[tid] = eidx[Ee + eb + tid];
    }
    s_r0[tid] = R0[tid];
    for (int p = tid; p < 4096; p += 512) s_B[p] = R1[p];
    __syncthreads();

    // ---- fused edge density ----
    if (tid < 64) {
        float t = 0.f;
#pragma unroll
        for (int k = 0; k < 8; k++) t += s_ef[tid * 8 + k] * __ldg(&Wd[k]);
        t *= 0.35355339059327373f;
        atomicAdd(&g_dens[s_ri[tid]], tanhf(t * t));
    }

    // ---- L1: At_a[c][e] = silu(ef[e] . R0[:,c] / sqrt(8)) ----
    for (int p = tid; p < 4096; p += 512) {
        int c = p >> 6, e = p & 63;
        float s = 0.f;
#pragma unroll
        for (int k = 0; k < 8; k++) s += s_ef[e * 8 + k] * s_r0[k * 64 + c];
        s *= 0.35355339059327373f;
        At_a[c * 68 + e] = s / (1.f + __expf(-s));
    }
    __syncthreads();

    const int te = tid & 15;   // e-tile: e0 = 4*te (covers 64)
    const int tc = tid >> 4;   // c-pair: c0 = 2*tc (covers 64)
    // ---- L2: At_b = silu(A1 @ R1 / 8)^T ----
    {
        float acc2[2][4];
#pragma unroll
        for (int q = 0; q < 2; q++)
#pragma unroll
            for (int i = 0; i < 4; i++) acc2[q][i] = 0.f;
#pragma unroll 8
        for (int k = 0; k < 64; k++) {
            float4 a = *(float4*)(At_a + k * 68 + te * 4);
            float2 b = *(float2*)(s_B + k * 64 + tc * 2);
            float av[4] = {a.x, a.y, a.z, a.w};
#pragma unroll
            for (int i = 0; i < 4; i++) {
                acc2[0][i] += av[i] * b.x;
                acc2[1][i] += av[i] * b.y;
            }
        }
#pragma unroll
        for (int q = 0; q < 2; q++) {
            float4 o;
            float s0 = acc2[q][0] * 0.125f, s1 = acc2[q][1] * 0.125f;
            float s2 = acc2[q][2] * 0.125f, s3 = acc2[q][3] * 0.125f;
            o.x = s0 / (1.f + __expf(-s0)); o.y = s1 / (1.f + __expf(-s1));
            o.z = s2 / (1.f + __expf(-s2)); o.w = s3 / (1.f + __expf(-s3));
            *(float4*)(At_b + (tc * 2 + q) * 68 + te * 4) = o;
        }
    }
    __syncthreads();
    for (int p = tid; p < 4096; p += 512) s_B[p] = R2[p];
    __syncthreads();
    // ---- L3: At_a = silu(A2 @ R2 / 8)^T ----
    {
        float acc2[2][4];
#pragma unroll
        for (int q = 0; q < 2; q++)
#pragma unroll
            for (int i = 0; i < 4; i++) acc2[q][i] = 0.f;
#pragma unroll 8
        for (int k = 0; k < 64; k++) {
            float4 a = *(float4*)(At_b + k * 68 + te * 4);
            float2 b = *(float2*)(s_B + k * 64 + tc * 2);
            float av[4] = {a.x, a.y, a.z, a.w};
#pragma unroll
            for (int i = 0; i < 4; i++) {
                acc2[0][i] += av[i] * b.x;
                acc2[1][i] += av[i] * b.y;
            }
        }
#pragma unroll
        for (int q = 0; q < 2; q++) {
            float4 o;
            float s0 = acc2[q][0] * 0.125f, s1 = acc2[q][1] * 0.125f;
            float s2 = acc2[q][2] * 0.125f, s3 = acc2[q][3] * 0.125f;
            o.x = s0 / (1.f + __expf(-s0)); o.y = s1 / (1.f + __expf(-s1));
            o.z = s2 / (1.f + __expf(-s2)); o.w = s3 / (1.f + __expf(-s3));
            *(float4*)(At_a + (tc * 2 + q) * 68 + te * 4) = o;
        }
    }
    __syncthreads();

    // ---- L4 chunks + register scatter (warp: 4 edges; lane: 4 channels) ----
    const int wrp = tid >> 5;       // 16 warps x 4 edges = 64
    const int lane = tid & 31;
    const int e0 = wrp * 4;
    const int u4 = lane * 4;

#pragma unroll
    for (int ch = 0; ch < 4; ch++) {
        for (int p = tid; p < 2048; p += 512) {
            int k = p >> 5, c4 = (p & 31) << 2;
            *(float4*)(s_B + k * 128 + c4) =
                *(const float4*)(R3 + (size_t)k * 512 + ch * 128 + c4);
        }
        __syncthreads();

        float acc[4][4];
#pragma unroll
        for (int i = 0; i < 4; i++)
#pragma unroll
            for (int q = 0; q < 4; q++) acc[i][q] = 0.f;
#pragma unroll 8
        for (int k = 0; k < 64; k++) {
            float4 a = *(float4*)(At_a + k * 68 + e0);
            float4 b = *(float4*)(s_B + k * 128 + u4);
            float av[4] = {a.x, a.y, a.z, a.w};
#pragma unroll
            for (int i = 0; i < 4; i++) {
                acc[i][0] += av[i] * b.x; acc[i][1] += av[i] * b.y;
                acc[i][2] += av[i] * b.z; acc[i][3] += av[i] * b.w;
            }
        }

#pragma unroll
        for (int i = 0; i < 4; i++) {
            int e = e0 + i;
            int s = s_si[e];
            int r = s_ri[e];
            float4 y = *(float4*)(s_y + e * 4);
            const float* hr = g_h + (size_t)s * 512;
            float* Mr = g_M + (size_t)r * 1024;
            float w0 = acc[i][0] * 0.125f, w1 = acc[i][1] * 0.125f;
            float w2 = acc[i][2] * 0.125f, w3 = acc[i][3] * 0.125f;
            if (ch == 0) {
                float4 h = *(const float4*)(hr + u4);
                RED4(Mr + u4, w0 * h.x * y.x, w1 * h.y * y.x,
                              w2 * h.z * y.x, w3 * h.w * y.x);
            } else if (ch == 1) {
                float4 h = *(const float4*)(hr + u4);
                float t0 = w0 * h.x, t1 = w1 * h.y, t2 = w2 * h.z, t3 = w3 * h.w;
                RED4(Mr + 256 + u4, t0 * y.y, t1 * y.y, t2 * y.y, t3 * y.y);
                RED4(Mr + 512 + u4, t0 * y.z, t1 * y.z, t2 * y.z, t3 * y.z);
                RED4(Mr + 768 + u4, t0 * y.w, t1 * y.w, t2 * y.w, t3 * y.w);
            } else if (ch == 2) {
                float4 ha = *(const float4*)(hr + 128 + u4);
                float4 hb = *(const float4*)(hr + 256 + u4);
                float4 hc = *(const float4*)(hr + 384 + u4);
                float wy0 = w0 * y.x, wy1 = w1 * y.x, wy2 = w2 * y.x, wy3 = w3 * y.x;
                RED4(Mr + 384 + u4, wy0 * ha.x, wy1 * ha.y, wy2 * ha.z, wy3 * ha.w);
                RED4(Mr + 640 + u4, wy0 * hb.x, wy1 * hb.y, wy2 * hb.z, wy3 * hb.w);
                RED4(Mr + 896 + u4, wy0 * hc.x, wy1 * hc.y, wy2 * hc.z, wy3 * hc.w);
            } else {
                float4 ha = *(const float4*)(hr + 128 + u4);
                float4 hb = *(const float4*)(hr + 256 + u4);
                float4 hc = *(const float4*)(hr + 384 + u4);
                const float c3 = 0.5773502691896258f;
                float d0 = ha.x * y.y + hb.x * y.z + hc.x * y.w;
                float d1 = ha.y * y.y + hb.y * y.z + hc.y * y.w;
                float d2 = ha.z * y.y + hb.z * y.z + hc.z * y.w;
                float d3 = ha.w * y.y + hb.w * y.z + hc.w * y.w;
                RED4(Mr + 128 + u4, w0 * d0 * c3, w1 * d1 * c3,
                                    w2 * d2 * c3, w3 * d3 * c3);
            }
        }
        __syncthreads();
    }
}

// ---------------- final linear (pipelined wmma) + density divide ----------
#define LIN_SM_TOTAL 147456       // 2 x TILE_BYTES
__global__ __launch_bounds__(512) void lin_kernel(float* __restrict__ msg_out) {
    extern __shared__ char smc[];
    char* tiles = smc;
    float* Dov = (float*)smc;

    const int tid = threadIdx.x;
    const int wid = tid >> 5;
    const int j = blockIdx.y;
    const int nb = blockIdx.x * 128;
    const int m0 = (wid & 7) * 16;
    const int nh = wid >> 3;
    const int sel = (j == 0) ? 0 : 1;

    int tn[4], tk[4];
#pragma unroll
    for (int i = 0; i < 4; i++) {
        int p = tid + i * 512;
        tn[i] = p >> 4;
        tk[i] = (p & 15) << 2;
    }

    wmma::fragment<wmma::accumulator, 16, 16, 16, float> facc[4];
    wmma::fragment<wmma::matrix_a, 16, 16, 16, __nv_bfloat16, wmma::row_major> fah, fal;
    wmma::fragment<wmma::matrix_b, 16, 16, 16, __nv_bfloat16, wmma::col_major> fbh, fbl;

    float4 a4[4];
    uint2  bhp[4], blp[4];

#pragma unroll
    for (int t = 0; t < 4; t++) wmma::fill_fragment(facc[t], 0.f);

    {
#pragma unroll
        for (int i = 0; i < 4; i++) {
            int gn = nb + tn[i];
            a4[i] = (gn < Nn)
                ? *(const float4*)(g_M + (size_t)gn * 1024 + j * 256 + tk[i])
                : make_float4(0.f, 0.f, 0.f, 0.f);
            bhp[i] = *(const uint2*)&g_BlnH[sel][0][tn[i]][tk[i]];
            blp[i] = *(const uint2*)&g_BlnL[sel][0][tn[i]][tk[i]];
        }
        __nv_bfloat16* Ahi = (__nv_bfloat16*)tiles;
        __nv_bfloat16* Alo = (__nv_bfloat16*)(tiles + 18432);
        __nv_bfloat16* Bhi = (__nv_bfloat16*)(tiles + 36864);
        __nv_bfloat16* Blo = (__nv_bfloat16*)(tiles + 55296);
#pragma unroll
        for (int i = 0; i < 4; i++) {
            int o = tn[i] * LDT + tk[i];
            __nv_bfloat16 h0, h1, h2, h3, l0, l1, l2, l3;
            bf16_split(a4[i].x, h0, l0); bf16_split(a4[i].y, h1, l1);
            bf16_split(a4[i].z, h2, l2); bf16_split(a4[i].w, h3, l3);
            Ahi[o] = h0; Ahi[o + 1] = h1; Ahi[o + 2] = h2; Ahi[o + 3] = h3;
            Alo[o] = l0; Alo[o + 1] = l1; Alo[o + 2] = l2; Alo[o + 3] = l3;
            *(uint2*)&Bhi[o] = bhp[i];
            *(uint2*)&Blo[o] = blp[i];
        }
    }
    __syncthreads();

    for (int c = 0; c < 4; c++) {
        const bool more = (c + 1) < 4;
        if (more) {
            const int cn = c + 1;
#pragma unroll
            for (int i = 0; i < 4; i++) {
                int gn = nb + tn[i];
                a4[i] = (gn < Nn)
                    ? *(const float4*)(g_M + (size_t)gn * 1024 + j * 256 + cn * 64 + tk[i])
                    : make_float4(0.f, 0.f, 0.f, 0.f);
                bhp[i] = *(const uint2*)&g_BlnH[sel][cn][tn[i]][tk[i]];
                blp[i] = *(const uint2*)&g_BlnL[sel][cn][tn[i]][tk[i]];
            }
        }
        {
            char* tb = tiles + (c & 1) * TILE_BYTES;
            __nv_bfloat16* Ahi = (__nv_bfloat16*)tb;
            __nv_bfloat16* Alo = (__nv_bfloat16*)(tb + 18432);
            __nv_bfloat16* Bhi = (__nv_bfloat16*)(tb + 36864);
            __nv_bfloat16* Blo = (__nv_bfloat16*)(tb + 55296);
#pragma unroll
            for (int kk = 0; kk < 4; kk++) {
                wmma::load_matrix_sync(fah, Ahi + m0 * LDT + kk * 16, LDT);
                wmma::load_matrix_sync(fal, Alo + m0 * LDT + kk * 16, LDT);
#pragma unroll
                for (int t = 0; t < 4; t++) {
                    int nt = nh * 4 + t;
                    wmma::load_matrix_sync(fbh, Bhi + nt * 16 * LDT + kk * 16, LDT);
                    wmma::load_matrix_sync(fbl, Blo + nt * 16 * LDT + kk * 16, LDT);
                    wmma::mma_sync(facc[t], fah, fbh, facc[t]);
                    wmma::mma_sync(facc[t], fah, fbl, facc[t]);
                    wmma::mma_sync(facc[t], fal, fbh, facc[t]);
                }
            }
        }
        if (more) {
            char* tb = tiles + ((c + 1) & 1) * TILE_BYTES;
            __nv_bfloat16* Ahi = (__nv_bfloat16*)tb;
            __nv_bfloat16* Alo = (__nv_bfloat16*)(tb + 18432);
            __nv_bfloat16* Bhi = (__nv_bfloat16*)(tb + 36864);
            __nv_bfloat16* Blo = (__nv_bfloat16*)(tb + 55296);
#pragma unroll
            for (int i = 0; i < 4; i++) {
                int o = tn[i] * LDT + tk[i];
                __nv_bfloat16 h0, h1, h2, h3, l0, l1, l2, l3;
                bf16_split(a4[i].x, h0, l0); bf16_split(a4[i].y, h1, l1);
                bf16_split(a4[i].z, h2, l2); bf16_split(a4[i].w, h3, l3);
                Ahi[o] = h0; Ahi[o + 1] = h1; Ahi[o + 2] = h2; Ahi[o + 3] = h3;
                Alo[o] = l0; Alo[o + 1] = l1; Alo[o + 2] = l2; Alo[o + 3] = l3;
                *(uint2*)&Bhi[o] = bhp[i];
                *(uint2*)&Blo[o] = blp[i];
            }
        }
        __syncthreads();
    }

#pragma unroll
    for (int t = 0; t < 4; t++)
        wmma::store_matrix_sync(Dov + m0 * 128 + nh * 64 + t * 16, facc[t], 128,
                                wmma::mem_row_major);
    __syncthreads();

    for (int p = tid; p < 16384; p += 512) {
        int n = p >> 7, v = p & 127;
        int gn = nb + n;
        if (gn < Nn) {
            float inv = 0.0625f / (g_dens[gn] + 1.f);  // 1/sqrt(256) / denom
            msg_out[(size_t)gn * 512 + (size_t)v * 4 + j] = Dov[n * 128 + v] * inv;
        }
    }
}

extern "C" void kernel_launch(void* const* d_in, const int* in_sizes, int n_in,
                              void* d_out, int out_size) {
    const float* na   = (const float*)d_in[0];
    const float* nf   = (const float*)d_in[1];
    const float* ea   = (const float*)d_in[2];
    const float* ef   = (const float*)d_in[3];
    const int*   eidx = (const int*)d_in[4];
    const float* Wup0 = (const float*)d_in[5];
    const float* Wup1 = (const float*)d_in[6];
    const float* R0   = (const float*)d_in[7];
    const float* R1   = (const float*)d_in[8];
    const float* R2   = (const float*)d_in[9];
    const float* R3   = (const float*)d_in[10];
    const float* Wd   = (const float*)d_in[11];
    const float* Wl0  = (const float*)d_in[12];
    const float* Wl1  = (const float*)d_in[13];
    const float* Wsk0 = (const float*)d_in[14];
    const float* Wsk1 = (const float*)d_in[15];
    float* out = (float*)d_out;
    float* msg_out = out;                       // message: (N,128,4)
    float* sc_out  = out + (size_t)Nn * 512;    // sc: (N,512)

    cudaFuncSetAttribute(node_up_kernel,   cudaFuncAttributeMaxDynamicSharedMemorySize, NK_SM_TOTAL);
    cudaFuncSetAttribute(node_skip_kernel, cudaFuncAttributeMaxDynamicSharedMemorySize, NK_SM_TOTAL);
    cudaFuncSetAttribute(edge_kernel, cudaFuncAttributeMaxDynamicSharedMemorySize, EG_SM_TOTAL);
    cudaFuncSetAttribute(lin_kernel,  cudaFuncAttributeMaxDynamicSharedMemorySize, LIN_SM_TOTAL);

    // Fork side stream FROM the capture-origin stream (capture-legal):
    cudaEventRecord(g_evF, 0);
    cudaStreamWaitEvent(g_s2, g_evF, 0);

    // side stream (low priority): prep_side -> node_skip  (independent chain)
    prep_side_kernel<<<296, 256, 0, g_s2>>>(Wsk0, Wsk1, Wl0, Wl1);
    cudaEventRecord(g_evP, g_s2);
    node_skip_kernel<<<dim3(79, 4), 1024, NK_SM_TOTAL, g_s2>>>(nf, na, sc_out);
    cudaEventRecord(g_evB, g_s2);

    // main stream: prep_main -> node_up -> edge -> lin
    prep_main_kernel<<<296, 256>>>(Wup0, Wup1);
    node_up_kernel<<<dim3(79, 4), 1024, NK_SM_TOTAL>>>(nf);
    edge_kernel<<<2000, 512, EG_SM_TOTAL>>>(ef, ea, eidx, Wd, R0, R1, R2, R3);
    cudaStreamWaitEvent(0, g_evP, 0);   // lin needs g_Bln from prep_side
    lin_kernel<<<dim3(79, 4), 512, LIN_SM_TOTAL>>>(msg_out);
    cudaStreamWaitEvent(0, g_evB, 0);   // join skip before harness reads d_out
}

// round 16
// speedup vs baseline: 1.0822x; 1.0822x over previous
#include <cuda_runtime.h>
#include <cuda_bf16.h>
#include <mma.h>
#include <math.h>
#include <stdint.h>

using namespace nvcuda;

#define Nn 10000
#define Ee 128000

// ---------------- scratch (device globals: allocation-free) ----------------
__device__ float g_h[(size_t)Nn * 512];   // [n][0:128]=h0, [128+k*128+u]=h1[u,k]
__device__ float g_M[(size_t)Nn * 1024];  // [n][j*256 + c] j=0:M0, j>0:M1[:,j-1]
__device__ float g_dens[Nn];

// pre-converted weights (bf16 hi/lo), chunk-major for conflict-free staging
__device__ __nv_bfloat16 g_BupH[2][2][128][64];   // [sel][chunk][v][kk]
__device__ __nv_bfloat16 g_BupL[2][2][128][64];
__device__ __nv_bfloat16 g_BskH[2][20][128][64];  // K reordered: k = a*128+u
__device__ __nv_bfloat16 g_BskL[2][20][128][64];
__device__ __nv_bfloat16 g_BlnH[2][4][128][64];   // W_lin: [sel][chunk][v][kk]
__device__ __nv_bfloat16 g_BlnL[2][4][128][64];

// ---------------- streams/events for graph fork (created pre-main) --------
static cudaStream_t g_s2;
static cudaEvent_t g_evF, g_evP, g_evB;
namespace {
struct StreamInit {
    StreamInit() {
        int lo = 0, hi = 0;
        cudaDeviceGetStreamPriorityRange(&lo, &hi);  // lo = least priority
        cudaStreamCreateWithPriority(&g_s2, cudaStreamNonBlocking, lo);
        cudaEventCreateWithFlags(&g_evF, cudaEventDisableTiming);
        cudaEventCreateWithFlags(&g_evP, cudaEventDisableTiming);
        cudaEventCreateWithFlags(&g_evB, cudaEventDisableTiming);
    }
};
StreamInit g_stream_init;
}

// 16B vector reduction (sm_90+)
#define RED4(p, va, vb, vc, vd)                                         \
    asm volatile("red.global.add.v4.f32 [%0], {%1, %2, %3, %4};"        \
                 :: "l"(p), "f"(va), "f"(vb), "f"(vc), "f"(vd) : "memory")

__device__ __forceinline__ void bf16_split(float v, __nv_bfloat16& h, __nv_bfloat16& l) {
    h = __float2bfloat16(v);
    l = __float2bfloat16(v - __bfloat162float(h));
}

// ---------------- prep (main): Bup conversion + accumulator clears --------
__global__ void prep_main_kernel(const float* __restrict__ Wup0,
                                 const float* __restrict__ Wup1) {
    int stride = gridDim.x * blockDim.x;
    int i = blockIdx.x * blockDim.x + threadIdx.x;
    for (int p = i; p < 32768; p += stride) {
        int kk = p & 63, v = (p >> 6) & 127, c = (p >> 13) & 1, sel = p >> 14;
        const float* W = sel ? Wup1 : Wup0;
        float val = W[(c * 64 + kk) * 128 + v];
        __nv_bfloat16 h, l; bf16_split(val, h, l);
        g_BupH[sel][c][v][kk] = h;
        g_BupL[sel][c][v][kk] = l;
    }
    float4 z = make_float4(0.f, 0.f, 0.f, 0.f);
    for (int p = i; p < Nn * 1024 / 4; p += stride) ((float4*)g_M)[p] = z;
    for (int p = i; p < Nn; p += stride) g_dens[p] = 0.f;
}

// ---------------- prep (side): Bsk + Bln conversions -----------------------
__global__ void prep_side_kernel(const float* __restrict__ Wsk0,
                                 const float* __restrict__ Wsk1,
                                 const float* __restrict__ Wl0,
                                 const float* __restrict__ Wl1) {
    int stride = gridDim.x * blockDim.x;
    int i = blockIdx.x * blockDim.x + threadIdx.x;
    for (int p = i; p < 327680; p += stride) {
        int sel = p >= 163840;
        int q = p - sel * 163840;
        int kk = q & 63, v = (q >> 6) & 127, c = q >> 13;  // c in 0..19
        int a = c >> 1, u = (c & 1) * 64 + kk;
        const float* W = sel ? Wsk1 : Wsk0;
        float val = W[u * 1280 + a * 128 + v];
        __nv_bfloat16 h, l; bf16_split(val, h, l);
        g_BskH[sel][c][v][kk] = h;
        g_BskL[sel][c][v][kk] = l;
    }
    for (int p = i; p < 65536; p += stride) {
        int kk = p & 63, v = (p >> 6) & 127, c = (p >> 13) & 3, sel = p >> 15;
        const float* W = sel ? Wl1 : Wl0;
        float val = W[(c * 64 + kk) * 128 + v];
        __nv_bfloat16 h, l; bf16_split(val, h, l);
        g_BlnH[sel][c][v][kk] = h;
        g_BlnL[sel][c][v][kk] = l;
    }
}

#define LDT 72
#define TILE_BYTES 73728
#define NK_SM_TOTAL 219136        // xs 65536 + ats 6144 + 2*73728

// ---------------- stage xs helper ------------------------------------------
__device__ __forceinline__ void stage_xs(float* xs, const float* __restrict__ nf,
                                         int j, int nb, int tid, int nthr) {
    if (j == 0) {
        for (int p = tid; p < 4096; p += nthr) {
            int n = p >> 5, u4 = (p & 31) << 2;
            int gn = nb + n;
            float4 v = make_float4(0.f, 0.f, 0.f, 0.f);
            if (gn < Nn) v = *(const float4*)(nf + (size_t)gn * 512 + u4);
            *(float4*)(xs + n * 128 + u4) = v;
        }
    } else {
        int kc2 = j - 1;
        for (int p = tid; p < 16384; p += nthr) {
            int n = p >> 7, u = p & 127;
            int gn = nb + n;
            xs[p] = (gn < Nn) ? nf[(size_t)gn * 512 + 128 + u * 3 + kc2] : 0.f;
        }
    }
}

// ---------------- node UP kernel: h = x @ Wup / sqrt(128) ------------------
__global__ __launch_bounds__(1024) void node_up_kernel(
        const float* __restrict__ nf) {
    extern __shared__ char smc[];
    float* xs = (float*)smc;
    char* tiles = smc + 71680;
    float* Dov = (float*)(smc + 71680);

    const int tid = threadIdx.x;
    const int wid = tid >> 5;
    const int j = blockIdx.y;
    const int nb = blockIdx.x * 128;
    const int m0 = (wid & 7) * 16;
    const int nq = wid >> 3;
    const int sel = (j == 0) ? 0 : 1;

    stage_xs(xs, nf, j, nb, tid, 1024);
    __syncthreads();

    int tn[2], tk[2];
#pragma unroll
    for (int i = 0; i < 2; i++) {
        int p = tid + i * 1024;
        tn[i] = p >> 4;
        tk[i] = (p & 15) << 2;
    }

    wmma::fragment<wmma::accumulator, 16, 16, 16, float> facc[2];
    wmma::fragment<wmma::matrix_a, 16, 16, 16, __nv_bfloat16, wmma::row_major> fah, fal;
    wmma::fragment<wmma::matrix_b, 16, 16, 16, __nv_bfloat16, wmma::col_major> fbh, fbl;
#pragma unroll
    for (int t = 0; t < 2; t++) wmma::fill_fragment(facc[t], 0.f);

    float4 a4[2];
    uint2 bhp[2], blp[2];

    {
#pragma unroll
        for (int i = 0; i < 2; i++) {
            a4[i] = *(float4*)(xs + tn[i] * 128 + tk[i]);
            bhp[i] = *(const uint2*)&g_BupH[sel][0][tn[i]][tk[i]];
            blp[i] = *(const uint2*)&g_BupL[sel][0][tn[i]][tk[i]];
        }
        __nv_bfloat16* Ahi = (__nv_bfloat16*)tiles;
        __nv_bfloat16* Alo = (__nv_bfloat16*)(tiles + 18432);
        __nv_bfloat16* Bhi = (__nv_bfloat16*)(tiles + 36864);
        __nv_bfloat16* Blo = (__nv_bfloat16*)(tiles + 55296);
#pragma unroll
        for (int i = 0; i < 2; i++) {
            int o = tn[i] * LDT + tk[i];
            __nv_bfloat16 h0, h1, h2, h3, l0, l1, l2, l3;
            bf16_split(a4[i].x, h0, l0); bf16_split(a4[i].y, h1, l1);
            bf16_split(a4[i].z, h2, l2); bf16_split(a4[i].w, h3, l3);
            Ahi[o] = h0; Ahi[o + 1] = h1; Ahi[o + 2] = h2; Ahi[o + 3] = h3;
            Alo[o] = l0; Alo[o + 1] = l1; Alo[o + 2] = l2; Alo[o + 3] = l3;
            *(uint2*)&Bhi[o] = bhp[i];
            *(uint2*)&Blo[o] = blp[i];
        }
    }
    __syncthreads();

    for (int c = 0; c < 2; c++) {
        const bool more = (c + 1) < 2;
        if (more) {
#pragma unroll
            for (int i = 0; i < 2; i++) {
                a4[i] = *(float4*)(xs + tn[i] * 128 + 64 + tk[i]);
                bhp[i] = *(const uint2*)&g_BupH[sel][1][tn[i]][tk[i]];
                blp[i] = *(const uint2*)&g_BupL[sel][1][tn[i]][tk[i]];
            }
        }
        {
            char* tb = tiles + (c & 1) * TILE_BYTES;
            __nv_bfloat16* Ahi = (__nv_bfloat16*)tb;
            __nv_bfloat16* Alo = (__nv_bfloat16*)(tb + 18432);
            __nv_bfloat16* Bhi = (__nv_bfloat16*)(tb + 36864);
            __nv_bfloat16* Blo = (__nv_bfloat16*)(tb + 55296);
#pragma unroll
            for (int kk = 0; kk < 4; kk++) {
                wmma::load_matrix_sync(fah, Ahi + m0 * LDT + kk * 16, LDT);
                wmma::load_matrix_sync(fal, Alo + m0 * LDT + kk * 16, LDT);
#pragma unroll
                for (int t = 0; t < 2; t++) {
                    int nt = nq * 2 + t;
                    wmma::load_matrix_sync(fbh, Bhi + nt * 16 * LDT + kk * 16, LDT);
                    wmma::load_matrix_sync(fbl, Blo + nt * 16 * LDT + kk * 16, LDT);
                    wmma::mma_sync(facc[t], fah, fbh, facc[t]);
                    wmma::mma_sync(facc[t], fah, fbl, facc[t]);
                    wmma::mma_sync(facc[t], fal, fbh, facc[t]);
                }
            }
        }
        if (more) {
            char* tb = tiles + ((c + 1) & 1) * TILE_BYTES;
            __nv_bfloat16* Ahi = (__nv_bfloat16*)tb;
            __nv_bfloat16* Alo = (__nv_bfloat16*)(tb + 18432);
            __nv_bfloat16* Bhi = (__nv_bfloat16*)(tb + 36864);
            __nv_bfloat16* Blo = (__nv_bfloat16*)(tb + 55296);
#pragma unroll
            for (int i = 0; i < 2; i++) {
                int o = tn[i] * LDT + tk[i];
                __nv_bfloat16 h0, h1, h2, h3, l0, l1, l2, l3;
                bf16_split(a4[i].x, h0, l0); bf16_split(a4[i].y, h1, l1);
                bf16_split(a4[i].z, h2, l2); bf16_split(a4[i].w, h3, l3);
                Ahi[o] = h0; Ahi[o + 1] = h1; Ahi[o + 2] = h2; Ahi[o + 3] = h3;
                Alo[o] = l0; Alo[o + 1] = l1; Alo[o + 2] = l2; Alo[o + 3] = l3;
                *(uint2*)&Bhi[o] = bhp[i];
                *(uint2*)&Blo[o] = blp[i];
            }
        }
        __syncthreads();
    }

#pragma unroll
    for (int t = 0; t < 2; t++)
        wmma::store_matrix_sync(Dov + m0 * 128 + nq * 32 + t * 16, facc[t], 128,
                                wmma::mem_row_major);
    __syncthreads();

    const float sh = 0.08838834764831845f;  // 1/sqrt(128)
    for (int p = tid; p < 4096; p += 1024) {
        int n = p >> 5, v4 = (p & 31) << 2;
        int gn = nb + n;
        if (gn < Nn) {
            float4 d = *(float4*)(Dov + n * 128 + v4);
            float4 o = make_float4(d.x * sh, d.y * sh, d.z * sh, d.w * sh);
            *(float4*)(g_h + (size_t)gn * 512 + j * 128 + v4) = o;
        }
    }
}

// ---------------- node SKIP kernel (independent of up/edge/lin) -------------
__global__ __launch_bounds__(1024) void node_skip_kernel(
        const float* __restrict__ nf, const float* __restrict__ na,
        float* __restrict__ sc_out) {
    extern __shared__ char smc[];
    float* xs  = (float*)smc;
    float* ats = (float*)(smc + 65536);
    char*  tiles = smc + 71680;
    float* Dov = (float*)(smc + 71680);

    const int tid = threadIdx.x;
    const int wid = tid >> 5;
    const int j = blockIdx.y;
    const int nb = blockIdx.x * 128;
    const int m0 = (wid & 7) * 16;
    const int nq = wid >> 3;
    const int sel = (j == 0) ? 0 : 1;

    stage_xs(xs, nf, j, nb, tid, 1024);
    for (int p = tid; p < 1280; p += 1024) {
        int n = p / 10, a = p - n * 10;
        int gn = nb + n;
        ats[n * 12 + a] = (gn < Nn) ? na[(size_t)gn * 10 + a] : 0.f;
    }
    __syncthreads();

    int tn[2], tk[2];
#pragma unroll
    for (int i = 0; i < 2; i++) {
        int p = tid + i * 1024;
        tn[i] = p >> 4;
        tk[i] = (p & 15) << 2;
    }

    wmma::fragment<wmma::accumulator, 16, 16, 16, float> facc[2];
    wmma::fragment<wmma::matrix_a, 16, 16, 16, __nv_bfloat16, wmma::row_major> fah, fal;
    wmma::fragment<wmma::matrix_b, 16, 16, 16, __nv_bfloat16, wmma::col_major> fbh, fbl;
#pragma unroll
    for (int t = 0; t < 2; t++) wmma::fill_fragment(facc[t], 0.f);

    float4 a4[2];
    float  atv[2];
    uint2  bhp[2], blp[2];

    {
#pragma unroll
        for (int i = 0; i < 2; i++) {
            a4[i] = *(float4*)(xs + tn[i] * 128 + tk[i]);
            atv[i] = ats[tn[i] * 12 + 0];
            bhp[i] = *(const uint2*)&g_BskH[sel][0][tn[i]][tk[i]];
            blp[i] = *(const uint2*)&g_BskL[sel][0][tn[i]][tk[i]];
        }
        __nv_bfloat16* Ahi = (__nv_bfloat16*)tiles;
        __nv_bfloat16* Alo = (__nv_bfloat16*)(tiles + 18432);
        __nv_bfloat16* Bhi = (__nv_bfloat16*)(tiles + 36864);
        __nv_bfloat16* Blo = (__nv_bfloat16*)(tiles + 55296);
#pragma unroll
        for (int i = 0; i < 2; i++) {
            int o = tn[i] * LDT + tk[i];
            __nv_bfloat16 h0, h1, h2, h3, l0, l1, l2, l3;
            bf16_split(a4[i].x * atv[i], h0, l0);
            bf16_split(a4[i].y * atv[i], h1, l1);
            bf16_split(a4[i].z * atv[i], h2, l2);
            bf16_split(a4[i].w * atv[i], h3, l3);
            Ahi[o] = h0; Ahi[o + 1] = h1; Ahi[o + 2] = h2; Ahi[o + 3] = h3;
            Alo[o] = l0; Alo[o + 1] = l1; Alo[o + 2] = l2; Alo[o + 3] = l3;
            *(uint2*)&Bhi[o] = bhp[i];
            *(uint2*)&Blo[o] = blp[i];
        }
    }
    __syncthreads();

    for (int c = 0; c < 20; c++) {
        const bool more = (c + 1) < 20;
        if (more) {
            const int cn = c + 1;
            const int xcol = (cn & 1) * 64;
            const int an = cn >> 1;
#pragma unroll
            for (int i = 0; i < 2; i++) {
                a4[i] = *(float4*)(xs + tn[i] * 128 + xcol + tk[i]);
                atv[i] = ats[tn[i] * 12 + an];
                bhp[i] = *(const uint2*)&g_BskH[sel][cn][tn[i]][tk[i]];
                blp[i] = *(const uint2*)&g_BskL[sel][cn][tn[i]][tk[i]];
            }
        }
        {
            char* tb = tiles + (c & 1) * TILE_BYTES;
            __nv_bfloat16* Ahi = (__nv_bfloat16*)tb;
            __nv_bfloat16* Alo = (__nv_bfloat16*)(tb + 18432);
            __nv_bfloat16* Bhi = (__nv_bfloat16*)(tb + 36864);
            __nv_bfloat16* Blo = (__nv_bfloat16*)(tb + 55296);
#pragma unroll
            for (int kk = 0; kk < 4; kk++) {
                wmma::load_matrix_sync(fah, Ahi + m0 * LDT + kk * 16, LDT);
                wmma::load_matrix_sync(fal, Alo + m0 * LDT + kk * 16, LDT);
#pragma unroll
                for (int t = 0; t < 2; t++) {
                    int nt = nq * 2 + t;
                    wmma::load_matrix_sync(fbh, Bhi + nt * 16 * LDT + kk * 16, LDT);
                    wmma::load_matrix_sync(fbl, Blo + nt * 16 * LDT + kk * 16, LDT);
                    wmma::mma_sync(facc[t], fah, fbh, facc[t]);
                    wmma::mma_sync(facc[t], fah, fbl, facc[t]);
                    wmma::mma_sync(facc[t], fal, fbh, facc[t]);
                }
            }
        }
        if (more) {
            char* tb = tiles + ((c + 1) & 1) * TILE_BYTES;
            __nv_bfloat16* Ahi = (__nv_bfloat16*)tb;
            __nv_bfloat16* Alo = (__nv_bfloat16*)(tb + 18432);
            __nv_bfloat16* Bhi = (__nv_bfloat16*)(tb + 36864);
            __nv_bfloat16* Blo = (__nv_bfloat16*)(tb + 55296);
#pragma unroll
            for (int i = 0; i < 2; i++) {
                int o = tn[i] * LDT + tk[i];
                __nv_bfloat16 h0, h1, h2, h3, l0, l1, l2, l3;
                bf16_split(a4[i].x * atv[i], h0, l0);
                bf16_split(a4[i].y * atv[i], h1, l1);
                bf16_split(a4[i].z * atv[i], h2, l2);
                bf16_split(a4[i].w * atv[i], h3, l3);
                Ahi[o] = h0; Ahi[o + 1] = h1; Ahi[o + 2] = h2; Ahi[o + 3] = h3;
                Alo[o] = l0; Alo[o + 1] = l1; Alo[o + 2] = l2; Alo[o + 3] = l3;
                *(uint2*)&Bhi[o] = bhp[i];
                *(uint2*)&Blo[o] = blp[i];
            }
        }
        __syncthreads();
    }

#pragma unroll
    for (int t = 0; t < 2; t++)
        wmma::store_matrix_sync(Dov + m0 * 128 + nq * 32 + t * 16, facc[t], 128,
                                wmma::mem_row_major);
    __syncthreads();

    const float ss = 0.027950849718747373f;  // 1/sqrt(1280)
    if (j == 0) {
        for (int p = tid; p < 4096; p += 1024) {
            int n = p >> 5, v4 = (p & 31) << 2;
            int gn = nb + n;
            if (gn < Nn) {
                float4 d = *(float4*)(Dov + n * 128 + v4);
                float4 o = make_float4(d.x * ss, d.y * ss, d.z * ss, d.w * ss);
                *(float4*)(sc_out + (size_t)gn * 512 + v4) = o;
            }
        }
    } else {
        for (int p = tid; p < 16384; p += 1024) {
            int n = p >> 7, v = p & 127;
            int gn = nb + n;
            if (gn < Nn)
                sc_out[(size_t)gn * 512 + 128 + v * 3 + (j - 1)] =
                    Dov[n * 128 + v] * ss;
        }
    }
}

// ---------------- fused edge kernel: density + MLP + register scatter ------
__global__ __launch_bounds__(512, 2) void edge_kernel(
        const float* __restrict__ ef, const float* __restrict__ ea,
        const int* __restrict__ eidx, const float* __restrict__ Wd,
        const float* __restrict__ R0, const float* __restrict__ R1,
        const float* __restrict__ R2, const float* __restrict__ R3) {
    extern __shared__ float sm[];
    float* s_ef = sm;                 // 1024
    float* s_r0 = sm + 1024;          // 512
    float* s_y  = sm + 1536;          // 512
    int*   s_si = (int*)(sm + 2048);  // 128
    int*   s_ri = (int*)(sm + 2176);  // 128
    float* At_a = sm + 2304;          // 8448
    float* At_b = At_a + 8448;        // 8448
    float* s_B  = At_b + 8448;        // 8448

    const int tid = threadIdx.x;
    const int eb = blockIdx.x * 128;

    for (int p = tid; p < 256; p += 512)
        ((float4*)s_ef)[p] = ((const float4*)(ef + (size_t)eb * 8))[p];
    for (int p = tid; p < 128; p += 512)
        ((float4*)s_y)[p] = ((const float4*)(ea + (size_t)eb * 4))[p];
    if (tid < 128) {
        s_si[tid] = eidx[eb + tid];
        s_ri[tid] = eidx[Ee + eb + tid];
    }
    s_r0[tid] = R0[tid];
    for (int p = tid; p < 4096; p += 512) s_B[p] = R1[p];
    __syncthreads();

    if (tid < 128) {
        float t = 0.f;
#pragma unroll
        for (int k = 0; k < 8; k++) t += s_ef[tid * 8 + k] * __ldg(&Wd[k]);
        t *= 0.35355339059327373f;
        atomicAdd(&g_dens[s_ri[tid]], tanhf(t * t));
    }

    for (int p = tid; p < 8192; p += 512) {
        int c = p >> 7, e = p & 127;
        float s = 0.f;
#pragma unroll
        for (int k = 0; k < 8; k++) s += s_ef[e * 8 + k] * s_r0[k * 64 + c];
        s *= 0.35355339059327373f;
        At_a[c * 132 + e] = s / (1.f + __expf(-s));
    }
    __syncthreads();

    const int te = tid & 31;
    const int tc = tid >> 5;
    // ---- L2 ----
    {
        float acc2[4][4];
#pragma unroll
        for (int i = 0; i < 4; i++)
#pragma unroll
            for (int q = 0; q < 4; q++) acc2[q][i] = 0.f;
#pragma unroll 8
        for (int k = 0; k < 64; k++) {
            float4 a = *(float4*)(At_a + k * 132 + te * 4);
            float4 b = *(float4*)(s_B + k * 64 + tc * 4);
            float av[4] = {a.x, a.y, a.z, a.w};
            float bv[4] = {b.x, b.y, b.z, b.w};
#pragma unroll
            for (int q = 0; q < 4; q++)
#pragma unroll
                for (int i = 0; i < 4; i++) acc2[q][i] += av[i] * bv[q];
        }
#pragma unroll
        for (int q = 0; q < 4; q++) {
            float4 o;
            float s0 = acc2[q][0] * 0.125f, s1 = acc2[q][1] * 0.125f;
            float s2 = acc2[q][2] * 0.125f, s3 = acc2[q][3] * 0.125f;
            o.x = s0 / (1.f + __expf(-s0)); o.y = s1 / (1.f + __expf(-s1));
            o.z = s2 / (1.f + __expf(-s2)); o.w = s3 / (1.f + __expf(-s3));
            *(float4*)(At_b + (tc * 4 + q) * 132 + te * 4) = o;
        }
    }
    __syncthreads();
    for (int p = tid; p < 4096; p += 512) s_B[p] = R2[p];
    __syncthreads();
    // ---- L3 ----
    {
        float acc2[4][4];
#pragma unroll
        for (int i = 0; i < 4; i++)
#pragma unroll
            for (int q = 0; q < 4; q++) acc2[q][i] = 0.f;
#pragma unroll 8
        for (int k = 0; k < 64; k++) {
            float4 a = *(float4*)(At_b + k * 132 + te * 4);
            float4 b = *(float4*)(s_B + k * 64 + tc * 4);
            float av[4] = {a.x, a.y, a.z, a.w};
            float bv[4] = {b.x, b.y, b.z, b.w};
#pragma unroll
            for (int q = 0; q < 4; q++)
#pragma unroll
                for (int i = 0; i < 4; i++) acc2[q][i] += av[i] * bv[q];
        }
#pragma unroll
        for (int q = 0; q < 4; q++) {
            float4 o;
            float s0 = acc2[q][0] * 0.125f, s1 = acc2[q][1] * 0.125f;
            float s2 = acc2[q][2] * 0.125f, s3 = acc2[q][3] * 0.125f;
            o.x = s0 / (1.f + __expf(-s0)); o.y = s1 / (1.f + __expf(-s1));
            o.z = s2 / (1.f + __expf(-s2)); o.w = s3 / (1.f + __expf(-s3));
            *(float4*)(At_a + (tc * 4 + q) * 132 + te * 4) = o;
        }
    }
    __syncthreads();

    // ---- L4 chunks + register scatter ----
    const int wrp = tid >> 5;
    const int lane = tid & 31;
    const int e0 = wrp * 8;
    const int u4 = lane * 4;

#pragma unroll
    for (int ch = 0; ch < 4; ch++) {
        for (int p = tid; p < 2048; p += 512) {
            int k = p >> 5, c4 = (p & 31) << 2;
            *(float4*)(s_B + k * 128 + c4) =
                *(const float4*)(R3 + (size_t)k * 512 + ch * 128 + c4);
        }
        __syncthreads();

        float acc[8][4];
#pragma unroll
        for (int i = 0; i < 8; i++)
#pragma unroll
            for (int q = 0; q < 4; q++) acc[i][q] = 0.f;
#pragma unroll 8
        for (int k = 0; k < 64; k++) {
            float4 a0 = *(float4*)(At_a + k * 132 + e0);
            float4 a1 = *(float4*)(At_a + k * 132 + e0 + 4);
            float4 b  = *(float4*)(s_B + k * 128 + u4);
            float av[8] = {a0.x, a0.y, a0.z, a0.w, a1.x, a1.y, a1.z, a1.w};
#pragma unroll
            for (int i = 0; i < 8; i++) {
                acc[i][0] += av[i] * b.x; acc[i][1] += av[i] * b.y;
                acc[i][2] += av[i] * b.z; acc[i][3] += av[i] * b.w;
            }
        }

#pragma unroll
        for (int i = 0; i < 8; i++) {
            int e = e0 + i;
            int s = s_si[e];
            int r = s_ri[e];
            float4 y = *(float4*)(s_y + e * 4);
            const float* hr = g_h + (size_t)s * 512;
            float* Mr = g_M + (size_t)r * 1024;
            float w0 = acc[i][0] * 0.125f, w1 = acc[i][1] * 0.125f;
            float w2 = acc[i][2] * 0.125f, w3 = acc[i][3] * 0.125f;
            if (ch == 0) {
                float4 h = *(const float4*)(hr + u4);
                RED4(Mr + u4, w0 * h.x * y.x, w1 * h.y * y.x,
                              w2 * h.z * y.x, w3 * h.w * y.x);
            } else if (ch == 1) {
                float4 h = *(const float4*)(hr + u4);
                float t0 = w0 * h.x, t1 = w1 * h.y, t2 = w2 * h.z, t3 = w3 * h.w;
                RED4(Mr + 256 + u4, t0 * y.y, t1 * y.y, t2 * y.y, t3 * y.y);
                RED4(Mr + 512 + u4, t0 * y.z, t1 * y.z, t2 * y.z, t3 * y.z);
                RED4(Mr + 768 + u4, t0 * y.w, t1 * y.w, t2 * y.w, t3 * y.w);
            } else if (ch == 2) {
                float4 ha = *(const float4*)(hr + 128 + u4);
                float4 hb = *(const float4*)(hr + 256 + u4);
                float4 hc = *(const float4*)(hr + 384 + u4);
                float wy0 = w0 * y.x, wy1 = w1 * y.x, wy2 = w2 * y.x, wy3 = w3 * y.x;
                RED4(Mr + 384 + u4, wy0 * ha.x, wy1 * ha.y, wy2 * ha.z, wy3 * ha.w);
                RED4(Mr + 640 + u4, wy0 * hb.x, wy1 * hb.y, wy2 * hb.z, wy3 * hb.w);
                RED4(Mr + 896 + u4, wy0 * hc.x, wy1 * hc.y, wy2 * hc.z, wy3 * hc.w);
            } else {
                float4 ha = *(const float4*)(hr + 128 + u4);
                float4 hb = *(const float4*)(hr + 256 + u4);
                float4 hc = *(const float4*)(hr + 384 + u4);
                const float c3 = 0.5773502691896258f;
                float d0 = ha.x * y.y + hb.x * y.z + hc.x * y.w;
                float d1 = ha.y * y.y + hb.y * y.z + hc.y * y.w;
                float d2 = ha.z * y.y + hb.z * y.z + hc.z * y.w;
                float d3 = ha.w * y.y + hb.w * y.z + hc.w * y.w;
                RED4(Mr + 128 + u4, w0 * d0 * c3, w1 * d1 * c3,
                                    w2 * d2 * c3, w3 * d3 * c3);
            }
        }
        __syncthreads();
    }
}

// ---------------- final linear (pipelined wmma) + density divide ----------
#define LIN_SM_TOTAL 147456       // 2 x TILE_BYTES
__global__ __launch_bounds__(512) void lin_kernel(float* __restrict__ msg_out) {
    extern __shared__ char smc[];
    char* tiles = smc;
    float* Dov = (float*)smc;

    const int tid = threadIdx.x;
    const int wid = tid >> 5;
    const int j = blockIdx.y;
    const int nb = blockIdx.x * 128;
    const int m0 = (wid & 7) * 16;
    const int nh = wid >> 3;
    const int sel = (j == 0) ? 0 : 1;

    int tn[4], tk[4];
#pragma unroll
    for (int i = 0; i < 4; i++) {
        int p = tid + i * 512;
        tn[i] = p >> 4;
        tk[i] = (p & 15) << 2;
    }

    wmma::fragment<wmma::accumulator, 16, 16, 16, float> facc[4];
    wmma::fragment<wmma::matrix_a, 16, 16, 16, __nv_bfloat16, wmma::row_major> fah, fal;
    wmma::fragment<wmma::matrix_b, 16, 16, 16, __nv_bfloat16, wmma::col_major> fbh, fbl;

    float4 a4[4];
    uint2  bhp[4], blp[4];

#pragma unroll
    for (int t = 0; t < 4; t++) wmma::fill_fragment(facc[t], 0.f);

    {
#pragma unroll
        for (int i = 0; i < 4; i++) {
            int gn = nb + tn[i];
            a4[i] = (gn < Nn)
                ? *(const float4*)(g_M + (size_t)gn * 1024 + j * 256 + tk[i])
                : make_float4(0.f, 0.f, 0.f, 0.f);
            bhp[i] = *(const uint2*)&g_BlnH[sel][0][tn[i]][tk[i]];
            blp[i] = *(const uint2*)&g_BlnL[sel][0][tn[i]][tk[i]];
        }
        __nv_bfloat16* Ahi = (__nv_bfloat16*)tiles;
        __nv_bfloat16* Alo = (__nv_bfloat16*)(tiles + 18432);
        __nv_bfloat16* Bhi = (__nv_bfloat16*)(tiles + 36864);
        __nv_bfloat16* Blo = (__nv_bfloat16*)(tiles + 55296);
#pragma unroll
        for (int i = 0; i < 4; i++) {
            int o = tn[i] * LDT + tk[i];
            __nv_bfloat16 h0, h1, h2, h3, l0, l1, l2, l3;
            bf16_split(a4[i].x, h0, l0); bf16_split(a4[i].y, h1, l1);
            bf16_split(a4[i].z, h2, l2); bf16_split(a4[i].w, h3, l3);
            Ahi[o] = h0; Ahi[o + 1] = h1; Ahi[o + 2] = h2; Ahi[o + 3] = h3;
            Alo[o] = l0; Alo[o + 1] = l1; Alo[o + 2] = l2; Alo[o + 3] = l3;
            *(uint2*)&Bhi[o] = bhp[i];
            *(uint2*)&Blo[o] = blp[i];
        }
    }
    __syncthreads();

    for (int c = 0; c < 4; c++) {
        const bool more = (c + 1) < 4;
        if (more) {
            const int cn = c + 1;
#pragma unroll
            for (int i = 0; i < 4; i++) {
                int gn = nb + tn[i];
                a4[i] = (gn < Nn)
                    ? *(const float4*)(g_M + (size_t)gn * 1024 + j * 256 + cn * 64 + tk[i])
                    : make_float4(0.f, 0.f, 0.f, 0.f);
                bhp[i] = *(const uint2*)&g_BlnH[sel][cn][tn[i]][tk[i]];
                blp[i] = *(const uint2*)&g_BlnL[sel][cn][tn[i]][tk[i]];
            }
        }
        {
            char* tb = tiles + (c & 1) * TILE_BYTES;
            __nv_bfloat16* Ahi = (__nv_bfloat16*)tb;
            __nv_bfloat16* Alo = (__nv_bfloat16*)(tb + 18432);
            __nv_bfloat16* Bhi = (__nv_bfloat16*)(tb + 36864);
            __nv_bfloat16* Blo = (__nv_bfloat16*)(tb + 55296);
#pragma unroll
            for (int kk = 0; kk < 4; kk++) {
                wmma::load_matrix_sync(fah, Ahi + m0 * LDT + kk * 16, LDT);
                wmma::load_matrix_sync(fal, Alo + m0 * LDT + kk * 16, LDT);
#pragma unroll
                for (int t = 0; t < 4; t++) {
                    int nt = nh * 4 + t;
                    wmma::load_matrix_sync(fbh, Bhi + nt * 16 * LDT + kk * 16, LDT);
                    wmma::load_matrix_sync(fbl, Blo + nt * 16 * LDT + kk * 16, LDT);
                    wmma::mma_sync(facc[t], fah, fbh, facc[t]);
                    wmma::mma_sync(facc[t], fah, fbl, facc[t]);
                    wmma::mma_sync(facc[t], fal, fbh, facc[t]);
                }
            }
        }
        if (more) {
            char* tb = tiles + ((c + 1) & 1) * TILE_BYTES;
            __nv_bfloat16* Ahi = (__nv_bfloat16*)tb;
            __nv_bfloat16* Alo = (__nv_bfloat16*)(tb + 18432);
            __nv_bfloat16* Bhi = (__nv_bfloat16*)(tb + 36864);
            __nv_bfloat16* Blo = (__nv_bfloat16*)(tb + 55296);
#pragma unroll
            for (int i = 0; i < 4; i++) {
                int o = tn[i] * LDT + tk[i];
                __nv_bfloat16 h0, h1, h2, h3, l0, l1, l2, l3;
                bf16_split(a4[i].x, h0, l0); bf16_split(a4[i].y, h1, l1);
                bf16_split(a4[i].z, h2, l2); bf16_split(a4[i].w, h3, l3);
                Ahi[o] = h0; Ahi[o + 1] = h1; Ahi[o + 2] = h2; Ahi[o + 3] = h3;
                Alo[o] = l0; Alo[o + 1] = l1; Alo[o + 2] = l2; Alo[o + 3] = l3;
                *(uint2*)&Bhi[o] = bhp[i];
                *(uint2*)&Blo[o] = blp[i];
            }
        }
        __syncthreads();
    }

#pragma unroll
    for (int t = 0; t < 4; t++)
        wmma::store_matrix_sync(Dov + m0 * 128 + nh * 64 + t * 16, facc[t], 128,
                                wmma::mem_row_major);
    __syncthreads();

    for (int p = tid; p < 16384; p += 512) {
        int n = p >> 7, v = p & 127;
        int gn = nb + n;
        if (gn < Nn) {
            float inv = 0.0625f / (g_dens[gn] + 1.f);  // 1/sqrt(256) / denom
            msg_out[(size_t)gn * 512 + (size_t)v * 4 + j] = Dov[n * 128 + v] * inv;
        }
    }
}

extern "C" void kernel_launch(void* const* d_in, const int* in_sizes, int n_in,
                              void* d_out, int out_size) {
    const float* na   = (const float*)d_in[0];
    const float* nf   = (const float*)d_in[1];
    const float* ea   = (const float*)d_in[2];
    const float* ef   = (const float*)d_in[3];
    const int*   eidx = (const int*)d_in[4];
    const float* Wup0 = (const float*)d_in[5];
    const float* Wup1 = (const float*)d_in[6];
    const float* R0   = (const float*)d_in[7];
    const float* R1   = (const float*)d_in[8];
    const float* R2   = (const float*)d_in[9];
    const float* R3   = (const float*)d_in[10];
    const float* Wd   = (const float*)d_in[11];
    const float* Wl0  = (const float*)d_in[12];
    const float* Wl1  = (const float*)d_in[13];
    const float* Wsk0 = (const float*)d_in[14];
    const float* Wsk1 = (const float*)d_in[15];
    float* out = (float*)d_out;
    float* msg_out = out;                       // message: (N,128,4)
    float* sc_out  = out + (size_t)Nn * 512;    // sc: (N,512)

    cudaFuncSetAttribute(node_up_kernel,   cudaFuncAttributeMaxDynamicSharedMemorySize, NK_SM_TOTAL);
    cudaFuncSetAttribute(node_skip_kernel, cudaFuncAttributeMaxDynamicSharedMemorySize, NK_SM_TOTAL);
    cudaFuncSetAttribute(edge_kernel, cudaFuncAttributeMaxDynamicSharedMemorySize, 110592);
    cudaFuncSetAttribute(lin_kernel,  cudaFuncAttributeMaxDynamicSharedMemorySize, LIN_SM_TOTAL);

    // Fork side stream FROM the capture-origin stream (capture-legal):
    cudaEventRecord(g_evF, 0);
    cudaStreamWaitEvent(g_s2, g_evF, 0);

    // side stream (low priority): prep_side -> node_skip  (independent chain)
    prep_side_kernel<<<296, 256, 0, g_s2>>>(Wsk0, Wsk1, Wl0, Wl1);
    cudaEventRecord(g_evP, g_s2);
    node_skip_kernel<<<dim3(79, 4), 1024, NK_SM_TOTAL, g_s2>>>(nf, na, sc_out);
    cudaEventRecord(g_evB, g_s2);

    // main stream: prep_main -> node_up -> edge -> lin
    prep_main_kernel<<<296, 256>>>(Wup0, Wup1);
    node_up_kernel<<<dim3(79, 4), 1024, NK_SM_TOTAL>>>(nf);
    edge_kernel<<<1000, 512, 110592>>>(ef, ea, eidx, Wd, R0, R1, R2, R3);
    cudaStreamWaitEvent(0, g_evP, 0);   // lin needs g_Bln from prep_side
    lin_kernel<<<dim3(79, 4), 512, LIN_SM_TOTAL>>>(msg_out);
    cudaStreamWaitEvent(0, g_evB, 0);   // join skip before harness reads d_out
}

// round 17
// speedup vs baseline: 1.1195x; 1.0344x over previous
#include <cuda_runtime.h>
#include <cuda_bf16.h>
#include <mma.h>
#include <math.h>
#include <stdint.h>

using namespace nvcuda;

#define Nn 10000
#define Ee 128000

// ---------------- scratch (device globals: allocation-free) ----------------
__device__ float g_h[(size_t)Nn * 512];   // [n][0:128]=h0, [128+k*128+u]=h1[u,k]
__device__ float g_M[(size_t)Nn * 1024];  // [n][j*256 + c] j=0:M0, j>0:M1[:,j-1]
__device__ float g_dens[Nn];

// pre-converted weights (bf16 hi/lo), chunk-major for conflict-free staging
__device__ __nv_bfloat16 g_BupH[2][2][128][64];   // [sel][chunk][v][kk]
__device__ __nv_bfloat16 g_BupL[2][2][128][64];
__device__ __nv_bfloat16 g_BskH[2][20][128][64];  // K reordered: k = a*128+u
__device__ __nv_bfloat16 g_BskL[2][20][128][64];
__device__ __nv_bfloat16 g_BlnH[2][4][128][64];   // W_lin: [sel][chunk][v][kk]
__device__ __nv_bfloat16 g_BlnL[2][4][128][64];

// ---------------- streams/events for graph fork (created pre-main) --------
static cudaStream_t g_s2;
static cudaEvent_t g_evF, g_evC, g_evP, g_evB;
namespace {
struct StreamInit {
    StreamInit() {
        int lo = 0, hi = 0;
        cudaDeviceGetStreamPriorityRange(&lo, &hi);  // lo = least priority
        cudaStreamCreateWithPriority(&g_s2, cudaStreamNonBlocking, lo);
        cudaEventCreateWithFlags(&g_evF, cudaEventDisableTiming);
        cudaEventCreateWithFlags(&g_evC, cudaEventDisableTiming);
        cudaEventCreateWithFlags(&g_evP, cudaEventDisableTiming);
        cudaEventCreateWithFlags(&g_evB, cudaEventDisableTiming);
    }
};
StreamInit g_stream_init;
}

// 16B vector reduction (sm_90+)
#define RED4(p, va, vb, vc, vd)                                         \
    asm volatile("red.global.add.v4.f32 [%0], {%1, %2, %3, %4};"        \
                 :: "l"(p), "f"(va), "f"(vb), "f"(vc), "f"(vd) : "memory")

__device__ __forceinline__ void bf16_split(float v, __nv_bfloat16& h, __nv_bfloat16& l) {
    h = __float2bfloat16(v);
    l = __float2bfloat16(v - __bfloat162float(h));
}

// ---------------- accumulator clears (side stream, overlaps node_up) ------
__global__ void clear_kernel() {
    int stride = gridDim.x * blockDim.x;
    int i = blockIdx.x * blockDim.x + threadIdx.x;
    float4 z = make_float4(0.f, 0.f, 0.f, 0.f);
    for (int p = i; p < Nn * 1024 / 4; p += stride) ((float4*)g_M)[p] = z;
    for (int p = i; p < Nn; p += stride) g_dens[p] = 0.f;
}

// ---------------- prep (main): Bup conversion only -------------------------
__global__ void prep_bup_kernel(const float* __restrict__ Wup0,
                                const float* __restrict__ Wup1) {
    int stride = gridDim.x * blockDim.x;
    int i = blockIdx.x * blockDim.x + threadIdx.x;
    for (int p = i; p < 32768; p += stride) {
        int kk = p & 63, v = (p >> 6) & 127, c = (p >> 13) & 1, sel = p >> 14;
        const float* W = sel ? Wup1 : Wup0;
        float val = W[(c * 64 + kk) * 128 + v];
        __nv_bfloat16 h, l; bf16_split(val, h, l);
        g_BupH[sel][c][v][kk] = h;
        g_BupL[sel][c][v][kk] = l;
    }
}

// ---------------- prep (side): Bsk + Bln conversions -----------------------
__global__ void prep_side_kernel(const float* __restrict__ Wsk0,
                                 const float* __restrict__ Wsk1,
                                 const float* __restrict__ Wl0,
                                 const float* __restrict__ Wl1) {
    int stride = gridDim.x * blockDim.x;
    int i = blockIdx.x * blockDim.x + threadIdx.x;
    for (int p = i; p < 327680; p += stride) {
        int sel = p >= 163840;
        int q = p - sel * 163840;
        int kk = q & 63, v = (q >> 6) & 127, c = q >> 13;  // c in 0..19
        int a = c >> 1, u = (c & 1) * 64 + kk;
        const float* W = sel ? Wsk1 : Wsk0;
        float val = W[u * 1280 + a * 128 + v];
        __nv_bfloat16 h, l; bf16_split(val, h, l);
        g_BskH[sel][c][v][kk] = h;
        g_BskL[sel][c][v][kk] = l;
    }
    for (int p = i; p < 65536; p += stride) {
        int kk = p & 63, v = (p >> 6) & 127, c = (p >> 13) & 3, sel = p >> 15;
        const float* W = sel ? Wl1 : Wl0;
        float val = W[(c * 64 + kk) * 128 + v];
        __nv_bfloat16 h, l; bf16_split(val, h, l);
        g_BlnH[sel][c][v][kk] = h;
        g_BlnL[sel][c][v][kk] = l;
    }
}

#define LDT 72
#define TILE_BYTES 73728
#define NK_SM_TOTAL 219136        // xs 65536 + ats 6144 + 2*73728 (skip only)
#define NU_SM_TOTAL 73728         // node_up: single tile buffer, no xs

// ---------------- stage xs helper (skip kernel only) -----------------------
__device__ __forceinline__ void stage_xs(float* xs, const float* __restrict__ nf,
                                         int j, int nb, int tid, int nthr) {
    if (j == 0) {
        for (int p = tid; p < 4096; p += nthr) {
            int n = p >> 5, u4 = (p & 31) << 2;
            int gn = nb + n;
            float4 v = make_float4(0.f, 0.f, 0.f, 0.f);
            if (gn < Nn) v = *(const float4*)(nf + (size_t)gn * 512 + u4);
            *(float4*)(xs + n * 128 + u4) = v;
        }
    } else {
        int kc2 = j - 1;
        for (int p = tid; p < 16384; p += nthr) {
            int n = p >> 7, u = p & 127;
            int gn = nb + n;
            xs[p] = (gn < Nn) ? nf[(size_t)gn * 512 + 128 + u * 3 + kc2] : 0.f;
        }
    }
}

// ---------------- node UP kernel: h = x @ Wup / sqrt(128) ------------------
// 512 threads, single 72KB tile buffer, A built DIRECTLY from global (each
// element read exactly once; no xs staging) -> 2 blocks/SM, 1.07 waves.
__global__ __launch_bounds__(512, 2) void node_up_kernel(
        const float* __restrict__ nf) {
    extern __shared__ char smc[];
    __nv_bfloat16* Ahi = (__nv_bfloat16*)smc;
    __nv_bfloat16* Alo = (__nv_bfloat16*)(smc + 18432);
    __nv_bfloat16* Bhi = (__nv_bfloat16*)(smc + 36864);
    __nv_bfloat16* Blo = (__nv_bfloat16*)(smc + 55296);
    float* Dov = (float*)smc;   // overlay after MMAs

    const int tid = threadIdx.x;
    const int wid = tid >> 5;
    const int j = blockIdx.y;
    const int nb = blockIdx.x * 128;
    const int m0 = (wid & 7) * 16;
    const int nh = wid >> 3;             // 0/1: n cols nh*64 .. nh*64+63
    const int sel = (j == 0) ? 0 : 1;

    int tn[4], tk[4];
#pragma unroll
    for (int i = 0; i < 4; i++) {
        int p = tid + i * 512;
        tn[i] = p >> 4;
        tk[i] = (p & 15) << 2;
    }

    wmma::fragment<wmma::accumulator, 16, 16, 16, float> facc[4];
    wmma::fragment<wmma::matrix_a, 16, 16, 16, __nv_bfloat16, wmma::row_major> fah, fal;
    wmma::fragment<wmma::matrix_b, 16, 16, 16, __nv_bfloat16, wmma::col_major> fbh, fbl;
#pragma unroll
    for (int t = 0; t < 4; t++) wmma::fill_fragment(facc[t], 0.f);

    for (int c = 0; c < 2; c++) {
        // ---- build A (direct global) + B (pre-converted) ----
#pragma unroll
        for (int i = 0; i < 4; i++) {
            int gn = nb + tn[i];
            float4 v = make_float4(0.f, 0.f, 0.f, 0.f);
            if (gn < Nn) {
                if (j == 0) {
                    v = *(const float4*)(nf + (size_t)gn * 512 + c * 64 + tk[i]);
                } else {
                    const float* base = nf + (size_t)gn * 512 + 128 + (j - 1);
                    int u0 = c * 64 + tk[i];
                    v.x = base[u0 * 3]; v.y = base[(u0 + 1) * 3];
                    v.z = base[(u0 + 2) * 3]; v.w = base[(u0 + 3) * 3];
                }
            }
            int o = tn[i] * LDT + tk[i];
            __nv_bfloat16 h0, h1, h2, h3, l0, l1, l2, l3;
            bf16_split(v.x, h0, l0); bf16_split(v.y, h1, l1);
            bf16_split(v.z, h2, l2); bf16_split(v.w, h3, l3);
            Ahi[o] = h0; Ahi[o + 1] = h1; Ahi[o + 2] = h2; Ahi[o + 3] = h3;
            Alo[o] = l0; Alo[o + 1] = l1; Alo[o + 2] = l2; Alo[o + 3] = l3;
            *(uint2*)&Bhi[o] = *(const uint2*)&g_BupH[sel][c][tn[i]][tk[i]];
            *(uint2*)&Blo[o] = *(const uint2*)&g_BupL[sel][c][tn[i]][tk[i]];
        }
        __syncthreads();
        // ---- MMA: 4 k16-steps x 4 n-tiles (this warp's half) x 3 passes ----
#pragma unroll
        for (int kk = 0; kk < 4; kk++) {
            wmma::load_matrix_sync(fah, Ahi + m0 * LDT + kk * 16, LDT);
            wmma::load_matrix_sync(fal, Alo + m0 * LDT + kk * 16, LDT);
#pragma unroll
            for (int t = 0; t < 4; t++) {
                int nt = nh * 4 + t;
                wmma::load_matrix_sync(fbh, Bhi + nt * 16 * LDT + kk * 16, LDT);
                wmma::load_matrix_sync(fbl, Blo + nt * 16 * LDT + kk * 16, LDT);
                wmma::mma_sync(facc[t], fah, fbh, facc[t]);
                wmma::mma_sync(facc[t], fah, fbl, facc[t]);
                wmma::mma_sync(facc[t], fal, fbh, facc[t]);
            }
        }
        __syncthreads();   // tiles reused (or overlaid) next iteration
    }

#pragma unroll
    for (int t = 0; t < 4; t++)
        wmma::store_matrix_sync(Dov + m0 * 128 + nh * 64 + t * 16, facc[t], 128,
                                wmma::mem_row_major);
    __syncthreads();

    const float sh = 0.08838834764831845f;  // 1/sqrt(128)
    for (int p = tid; p < 4096; p += 512) {
        int n = p >> 5, v4 = (p & 31) << 2;
        int gn = nb + n;
        if (gn < Nn) {
            float4 d = *(float4*)(Dov + n * 128 + v4);
            float4 o = make_float4(d.x * sh, d.y * sh, d.z * sh, d.w * sh);
            *(float4*)(g_h + (size_t)gn * 512 + j * 128 + v4) = o;
        }
    }
}

// ---------------- node SKIP kernel (independent of up/edge/lin) -------------
__global__ __launch_bounds__(1024) void node_skip_kernel(
        const float* __restrict__ nf, const float* __restrict__ na,
        float* __restrict__ sc_out) {
    extern __shared__ char smc[];
    float* xs  = (float*)smc;
    float* ats = (float*)(smc + 65536);
    char*  tiles = smc + 71680;
    float* Dov = (float*)(smc + 71680);

    const int tid = threadIdx.x;
    const int wid = tid >> 5;
    const int j = blockIdx.y;
    const int nb = blockIdx.x * 128;
    const int m0 = (wid & 7) * 16;
    const int nq = wid >> 3;
    const int sel = (j == 0) ? 0 : 1;

    stage_xs(xs, nf, j, nb, tid, 1024);
    for (int p = tid; p < 1280; p += 1024) {
        int n = p / 10, a = p - n * 10;
        int gn = nb + n;
        ats[n * 12 + a] = (gn < Nn) ? na[(size_t)gn * 10 + a] : 0.f;
    }
    __syncthreads();

    int tn[2], tk[2];
#pragma unroll
    for (int i = 0; i < 2; i++) {
        int p = tid + i * 1024;
        tn[i] = p >> 4;
        tk[i] = (p & 15) << 2;
    }

    wmma::fragment<wmma::accumulator, 16, 16, 16, float> facc[2];
    wmma::fragment<wmma::matrix_a, 16, 16, 16, __nv_bfloat16, wmma::row_major> fah, fal;
    wmma::fragment<wmma::matrix_b, 16, 16, 16, __nv_bfloat16, wmma::col_major> fbh, fbl;
#pragma unroll
    for (int t = 0; t < 2; t++) wmma::fill_fragment(facc[t], 0.f);

    float4 a4[2];
    float  atv[2];
    uint2  bhp[2], blp[2];

    {
#pragma unroll
        for (int i = 0; i < 2; i++) {
            a4[i] = *(float4*)(xs + tn[i] * 128 + tk[i]);
            atv[i] = ats[tn[i] * 12 + 0];
            bhp[i] = *(const uint2*)&g_BskH[sel][0][tn[i]][tk[i]];
            blp[i] = *(const uint2*)&g_BskL[sel][0][tn[i]][tk[i]];
        }
        __nv_bfloat16* Ahi = (__nv_bfloat16*)tiles;
        __nv_bfloat16* Alo = (__nv_bfloat16*)(tiles + 18432);
        __nv_bfloat16* Bhi = (__nv_bfloat16*)(tiles + 36864);
        __nv_bfloat16* Blo = (__nv_bfloat16*)(tiles + 55296);
#pragma unroll
        for (int i = 0; i < 2; i++) {
            int o = tn[i] * LDT + tk[i];
            __nv_bfloat16 h0, h1, h2, h3, l0, l1, l2, l3;
            bf16_split(a4[i].x * atv[i], h0, l0);
            bf16_split(a4[i].y * atv[i], h1, l1);
            bf16_split(a4[i].z * atv[i], h2, l2);
            bf16_split(a4[i].w * atv[i], h3, l3);
            Ahi[o] = h0; Ahi[o + 1] = h1; Ahi[o + 2] = h2; Ahi[o + 3] = h3;
            Alo[o] = l0; Alo[o + 1] = l1; Alo[o + 2] = l2; Alo[o + 3] = l3;
            *(uint2*)&Bhi[o] = bhp[i];
            *(uint2*)&Blo[o] = blp[i];
        }
    }
    __syncthreads();

    for (int c = 0; c < 20; c++) {
        const bool more = (c + 1) < 20;
        if (more) {
            const int cn = c + 1;
            const int xcol = (cn & 1) * 64;
            const int an = cn >> 1;
#pragma unroll
            for (int i = 0; i < 2; i++) {
                a4[i] = *(float4*)(xs + tn[i] * 128 + xcol + tk[i]);
                atv[i] = ats[tn[i] * 12 + an];
                bhp[i] = *(const uint2*)&g_BskH[sel][cn][tn[i]][tk[i]];
                blp[i] = *(const uint2*)&g_BskL[sel][cn][tn[i]][tk[i]];
            }
        }
        {
            char* tb = tiles + (c & 1) * TILE_BYTES;
            __nv_bfloat16* Ahi = (__nv_bfloat16*)tb;
            __nv_bfloat16* Alo = (__nv_bfloat16*)(tb + 18432);
            __nv_bfloat16* Bhi = (__nv_bfloat16*)(tb + 36864);
            __nv_bfloat16* Blo = (__nv_bfloat16*)(tb + 55296);
#pragma unroll
            for (int kk = 0; kk < 4; kk++) {
                wmma::load_matrix_sync(fah, Ahi + m0 * LDT + kk * 16, LDT);
                wmma::load_matrix_sync(fal, Alo + m0 * LDT + kk * 16, LDT);
#pragma unroll
                for (int t = 0; t < 2; t++) {
                    int nt = nq * 2 + t;
                    wmma::load_matrix_sync(fbh, Bhi + nt * 16 * LDT + kk * 16, LDT);
                    wmma::load_matrix_sync(fbl, Blo + nt * 16 * LDT + kk * 16, LDT);
                    wmma::mma_sync(facc[t], fah, fbh, facc[t]);
                    wmma::mma_sync(facc[t], fah, fbl, facc[t]);
                    wmma::mma_sync(facc[t], fal, fbh, facc[t]);
                }
            }
        }
        if (more) {
            char* tb = tiles + ((c + 1) & 1) * TILE_BYTES;
            __nv_bfloat16* Ahi = (__nv_bfloat16*)tb;
            __nv_bfloat16* Alo = (__nv_bfloat16*)(tb + 18432);
            __nv_bfloat16* Bhi = (__nv_bfloat16*)(tb + 36864);
            __nv_bfloat16* Blo = (__nv_bfloat16*)(tb + 55296);
#pragma unroll
            for (int i = 0; i < 2; i++) {
                int o = tn[i] * LDT + tk[i];
                __nv_bfloat16 h0, h1, h2, h3, l0, l1, l2, l3;
                bf16_split(a4[i].x * atv[i], h0, l0);
                bf16_split(a4[i].y * atv[i], h1, l1);
                bf16_split(a4[i].z * atv[i], h2, l2);
                bf16_split(a4[i].w * atv[i], h3, l3);
                Ahi[o] = h0; Ahi[o + 1] = h1; Ahi[o + 2] = h2; Ahi[o + 3] = h3;
                Alo[o] = l0; Alo[o + 1] = l1; Alo[o + 2] = l2; Alo[o + 3] = l3;
                *(uint2*)&Bhi[o] = bhp[i];
                *(uint2*)&Blo[o] = blp[i];
            }
        }
        __syncthreads();
    }

#pragma unroll
    for (int t = 0; t < 2; t++)
        wmma::store_matrix_sync(Dov + m0 * 128 + nq * 32 + t * 16, facc[t], 128,
                                wmma::mem_row_major);
    __syncthreads();

    const float ss = 0.027950849718747373f;  // 1/sqrt(1280)
    if (j == 0) {
        for (int p = tid; p < 4096; p += 1024) {
            int n = p >> 5, v4 = (p & 31) << 2;
            int gn = nb + n;
            if (gn < Nn) {
                float4 d = *(float4*)(Dov + n * 128 + v4);
                float4 o = make_float4(d.x * ss, d.y * ss, d.z * ss, d.w * ss);
                *(float4*)(sc_out + (size_t)gn * 512 + v4) = o;
            }
        }
    } else {
        for (int p = tid; p < 16384; p += 1024) {
            int n = p >> 7, v = p & 127;
            int gn = nb + n;
            if (gn < Nn)
                sc_out[(size_t)gn * 512 + 128 + v * 3 + (j - 1)] =
                    Dov[n * 128 + v] * ss;
        }
    }
}

// ---------------- fused edge kernel: density + MLP + register scatter ------
__global__ __launch_bounds__(512, 2) void edge_kernel(
        const float* __restrict__ ef, const float* __restrict__ ea,
        const int* __restrict__ eidx, const float* __restrict__ Wd,
        const float* __restrict__ R0, const float* __restrict__ R1,
        const float* __restrict__ R2, const float* __restrict__ R3) {
    extern __shared__ float sm[];
    float* s_ef = sm;                 // 1024
    float* s_r0 = sm + 1024;          // 512
    float* s_y  = sm + 1536;          // 512
    int*   s_si = (int*)(sm + 2048);  // 128
    int*   s_ri = (int*)(sm + 2176);  // 128
    float* At_a = sm + 2304;          // 8448
    float* At_b = At_a + 8448;        // 8448
    float* s_B  = At_b + 8448;        // 8448

    const int tid = threadIdx.x;
    const int eb = blockIdx.x * 128;

    for (int p = tid; p < 256; p += 512)
        ((float4*)s_ef)[p] = ((const float4*)(ef + (size_t)eb * 8))[p];
    for (int p = tid; p < 128; p += 512)
        ((float4*)s_y)[p] = ((const float4*)(ea + (size_t)eb * 4))[p];
    if (tid < 128) {
        s_si[tid] = eidx[eb + tid];
        s_ri[tid] = eidx[Ee + eb + tid];
    }
    s_r0[tid] = R0[tid];
    for (int p = tid; p < 4096; p += 512) s_B[p] = R1[p];
    __syncthreads();

    if (tid < 128) {
        float t = 0.f;
#pragma unroll
        for (int k = 0; k < 8; k++) t += s_ef[tid * 8 + k] * __ldg(&Wd[k]);
        t *= 0.35355339059327373f;
        atomicAdd(&g_dens[s_ri[tid]], tanhf(t * t));
    }

    for (int p = tid; p < 8192; p += 512) {
        int c = p >> 7, e = p & 127;
        float s = 0.f;
#pragma unroll
        for (int k = 0; k < 8; k++) s += s_ef[e * 8 + k] * s_r0[k * 64 + c];
        s *= 0.35355339059327373f;
        At_a[c * 132 + e] = s / (1.f + __expf(-s));
    }
    __syncthreads();

    const int te = tid & 31;
    const int tc = tid >> 5;
    // ---- L2 ----
    {
        float acc2[4][4];
#pragma unroll
        for (int i = 0; i < 4; i++)
#pragma unroll
            for (int q = 0; q < 4; q++) acc2[q][i] = 0.f;
#pragma unroll 8
        for (int k = 0; k < 64; k++) {
            float4 a = *(float4*)(At_a + k * 132 + te * 4);
            float4 b = *(float4*)(s_B + k * 64 + tc * 4);
            float av[4] = {a.x, a.y, a.z, a.w};
            float bv[4] = {b.x, b.y, b.z, b.w};
#pragma unroll
            for (int q = 0; q < 4; q++)
#pragma unroll
                for (int i = 0; i < 4; i++) acc2[q][i] += av[i] * bv[q];
        }
#pragma unroll
        for (int q = 0; q < 4; q++) {
            float4 o;
            float s0 = acc2[q][0] * 0.125f, s1 = acc2[q][1] * 0.125f;
            float s2 = acc2[q][2] * 0.125f, s3 = acc2[q][3] * 0.125f;
            o.x = s0 / (1.f + __expf(-s0)); o.y = s1 / (1.f + __expf(-s1));
            o.z = s2 / (1.f + __expf(-s2)); o.w = s3 / (1.f + __expf(-s3));
            *(float4*)(At_b + (tc * 4 + q) * 132 + te * 4) = o;
        }
    }
    __syncthreads();
    for (int p = tid; p < 4096; p += 512) s_B[p] = R2[p];
    __syncthreads();
    // ---- L3 ----
    {
        float acc2[4][4];
#pragma unroll
        for (int i = 0; i < 4; i++)
#pragma unroll
            for (int q = 0; q < 4; q++) acc2[q][i] = 0.f;
#pragma unroll 8
        for (int k = 0; k < 64; k++) {
            float4 a = *(float4*)(At_b + k * 132 + te * 4);
            float4 b = *(float4*)(s_B + k * 64 + tc * 4);
            float av[4] = {a.x, a.y, a.z, a.w};
            float bv[4] = {b.x, b.y, b.z, b.w};
#pragma unroll
            for (int q = 0; q < 4; q++)
#pragma unroll
                for (int i = 0; i < 4; i++) acc2[q][i] += av[i] * bv[q];
        }
#pragma unroll
        for (int q = 0; q < 4; q++) {
            float4 o;
            float s0 = acc2[q][0] * 0.125f, s1 = acc2[q][1] * 0.125f;
            float s2 = acc2[q][2] * 0.125f, s3 = acc2[q][3] * 0.125f;
            o.x = s0 / (1.f + __expf(-s0)); o.y = s1 / (1.f + __expf(-s1));
            o.z = s2 / (1.f + __expf(-s2)); o.w = s3 / (1.f + __expf(-s3));
            *(float4*)(At_a + (tc * 4 + q) * 132 + te * 4) = o;
        }
    }
    __syncthreads();

    // ---- L4 chunks + register scatter ----
    const int wrp = tid >> 5;
    const int lane = tid & 31;
    const int e0 = wrp * 8;
    const int u4 = lane * 4;

#pragma unroll
    for (int ch = 0; ch < 4; ch++) {
        for (int p = tid; p < 2048; p += 512) {
            int k = p >> 5, c4 = (p & 31) << 2;
            *(float4*)(s_B + k * 128 + c4) =
                *(const float4*)(R3 + (size_t)k * 512 + ch * 128 + c4);
        }
        __syncthreads();

        float acc[8][4];
#pragma unroll
        for (int i = 0; i < 8; i++)
#pragma unroll
            for (int q = 0; q < 4; q++) acc[i][q] = 0.f;
#pragma unroll 8
        for (int k = 0; k < 64; k++) {
            float4 a0 = *(float4*)(At_a + k * 132 + e0);
            float4 a1 = *(float4*)(At_a + k * 132 + e0 + 4);
            float4 b  = *(float4*)(s_B + k * 128 + u4);
            float av[8] = {a0.x, a0.y, a0.z, a0.w, a1.x, a1.y, a1.z, a1.w};
#pragma unroll
            for (int i = 0; i < 8; i++) {
                acc[i][0] += av[i] * b.x; acc[i][1] += av[i] * b.y;
                acc[i][2] += av[i] * b.z; acc[i][3] += av[i] * b.w;
            }
        }

#pragma unroll
        for (int i = 0; i < 8; i++) {
            int e = e0 + i;
            int s = s_si[e];
            int r = s_ri[e];
            float4 y = *(float4*)(s_y + e * 4);
            const float* hr = g_h + (size_t)s * 512;
            float* Mr = g_M + (size_t)r * 1024;
            float w0 = acc[i][0] * 0.125f, w1 = acc[i][1] * 0.125f;
            float w2 = acc[i][2] * 0.125f, w3 = acc[i][3] * 0.125f;
            if (ch == 0) {
                float4 h = *(const float4*)(hr + u4);
                RED4(Mr + u4, w0 * h.x * y.x, w1 * h.y * y.x,
                              w2 * h.z * y.x, w3 * h.w * y.x);
            } else if (ch == 1) {
                float4 h = *(const float4*)(hr + u4);
                float t0 = w0 * h.x, t1 = w1 * h.y, t2 = w2 * h.z, t3 = w3 * h.w;
                RED4(Mr + 256 + u4, t0 * y.y, t1 * y.y, t2 * y.y, t3 * y.y);
                RED4(Mr + 512 + u4, t0 * y.z, t1 * y.z, t2 * y.z, t3 * y.z);
                RED4(Mr + 768 + u4, t0 * y.w, t1 * y.w, t2 * y.w, t3 * y.w);
            } else if (ch == 2) {
                float4 ha = *(const float4*)(hr + 128 + u4);
                float4 hb = *(const float4*)(hr + 256 + u4);
                float4 hc = *(const float4*)(hr + 384 + u4);
                float wy0 = w0 * y.x, wy1 = w1 * y.x, wy2 = w2 * y.x, wy3 = w3 * y.x;
                RED4(Mr + 384 + u4, wy0 * ha.x, wy1 * ha.y, wy2 * ha.z, wy3 * ha.w);
                RED4(Mr + 640 + u4, wy0 * hb.x, wy1 * hb.y, wy2 * hb.z, wy3 * hb.w);
                RED4(Mr + 896 + u4, wy0 * hc.x, wy1 * hc.y, wy2 * hc.z, wy3 * hc.w);
            } else {
                float4 ha = *(const float4*)(hr + 128 + u4);
                float4 hb = *(const float4*)(hr + 256 + u4);
                float4 hc = *(const float4*)(hr + 384 + u4);
                const float c3 = 0.5773502691896258f;
                float d0 = ha.x * y.y + hb.x * y.z + hc.x * y.w;
                float d1 = ha.y * y.y + hb.y * y.z + hc.y * y.w;
                float d2 = ha.z * y.y + hb.z * y.z + hc.z * y.w;
                float d3 = ha.w * y.y + hb.w * y.z + hc.w * y.w;
                RED4(Mr + 128 + u4, w0 * d0 * c3, w1 * d1 * c3,
                                    w2 * d2 * c3, w3 * d3 * c3);
            }
        }
        __syncthreads();
    }
}

// ---------------- final linear (pipelined wmma) + density divide ----------
#define LIN_SM_TOTAL 147456       // 2 x TILE_BYTES
__global__ __launch_bounds__(512) void lin_kernel(float* __restrict__ msg_out) {
    extern __shared__ char smc[];
    char* tiles = smc;
    float* Dov = (float*)smc;

    const int tid = threadIdx.x;
    const int wid = tid >> 5;
    const int j = blockIdx.y;
    const int nb = blockIdx.x * 128;
    const int m0 = (wid & 7) * 16;
    const int nh = wid >> 3;
    const int sel = (j == 0) ? 0 : 1;

    int tn[4], tk[4];
#pragma unroll
    for (int i = 0; i < 4; i++) {
        int p = tid + i * 512;
        tn[i] = p >> 4;
        tk[i] = (p & 15) << 2;
    }

    wmma::fragment<wmma::accumulator, 16, 16, 16, float> facc[4];
    wmma::fragment<wmma::matrix_a, 16, 16, 16, __nv_bfloat16, wmma::row_major> fah, fal;
    wmma::fragment<wmma::matrix_b, 16, 16, 16, __nv_bfloat16, wmma::col_major> fbh, fbl;

    float4 a4[4];
    uint2  bhp[4], blp[4];

#pragma unroll
    for (int t = 0; t < 4; t++) wmma::fill_fragment(facc[t], 0.f);

    {
#pragma unroll
        for (int i = 0; i < 4; i++) {
            int gn = nb + tn[i];
            a4[i] = (gn < Nn)
                ? *(const float4*)(g_M + (size_t)gn * 1024 + j * 256 + tk[i])
                : make_float4(0.f, 0.f, 0.f, 0.f);
            bhp[i] = *(const uint2*)&g_BlnH[sel][0][tn[i]][tk[i]];
            blp[i] = *(const uint2*)&g_BlnL[sel][0][tn[i]][tk[i]];
        }
        __nv_bfloat16* Ahi = (__nv_bfloat16*)tiles;
        __nv_bfloat16* Alo = (__nv_bfloat16*)(tiles + 18432);
        __nv_bfloat16* Bhi = (__nv_bfloat16*)(tiles + 36864);
        __nv_bfloat16* Blo = (__nv_bfloat16*)(tiles + 55296);
#pragma unroll
        for (int i = 0; i < 4; i++) {
            int o = tn[i] * LDT + tk[i];
            __nv_bfloat16 h0, h1, h2, h3, l0, l1, l2, l3;
            bf16_split(a4[i].x, h0, l0); bf16_split(a4[i].y, h1, l1);
            bf16_split(a4[i].z, h2, l2); bf16_split(a4[i].w, h3, l3);
            Ahi[o] = h0; Ahi[o + 1] = h1; Ahi[o + 2] = h2; Ahi[o + 3] = h3;
            Alo[o] = l0; Alo[o + 1] = l1; Alo[o + 2] = l2; Alo[o + 3] = l3;
            *(uint2*)&Bhi[o] = bhp[i];
            *(uint2*)&Blo[o] = blp[i];
        }
    }
    __syncthreads();

    for (int c = 0; c < 4; c++) {
        const bool more = (c + 1) < 4;
        if (more) {
            const int cn = c + 1;
#pragma unroll
            for (int i = 0; i < 4; i++) {
                int gn = nb + tn[i];
                a4[i] = (gn < Nn)
                    ? *(const float4*)(g_M + (size_t)gn * 1024 + j * 256 + cn * 64 + tk[i])
                    : make_float4(0.f, 0.f, 0.f, 0.f);
                bhp[i] = *(const uint2*)&g_BlnH[sel][cn][tn[i]][tk[i]];
                blp[i] = *(const uint2*)&g_BlnL[sel][cn][tn[i]][tk[i]];
            }
        }
        {
            char* tb = tiles + (c & 1) * TILE_BYTES;
            __nv_bfloat16* Ahi = (__nv_bfloat16*)tb;
            __nv_bfloat16* Alo = (__nv_bfloat16*)(tb + 18432);
            __nv_bfloat16* Bhi = (__nv_bfloat16*)(tb + 36864);
            __nv_bfloat16* Blo = (__nv_bfloat16*)(tb + 55296);
#pragma unroll
            for (int kk = 0; kk < 4; kk++) {
                wmma::load_matrix_sync(fah, Ahi + m0 * LDT + kk * 16, LDT);
                wmma::load_matrix_sync(fal, Alo + m0 * LDT + kk * 16, LDT);
#pragma unroll
                for (int t = 0; t < 4; t++) {
                    int nt = nh * 4 + t;
                    wmma::load_matrix_sync(fbh, Bhi + nt * 16 * LDT + kk * 16, LDT);
                    wmma::load_matrix_sync(fbl, Blo + nt * 16 * LDT + kk * 16, LDT);
                    wmma::mma_sync(facc[t], fah, fbh, facc[t]);
                    wmma::mma_sync(facc[t], fah, fbl, facc[t]);
                    wmma::mma_sync(facc[t], fal, fbh, facc[t]);
                }
            }
        }
        if (more) {
            char* tb = tiles + ((c + 1) & 1) * TILE_BYTES;
            __nv_bfloat16* Ahi = (__nv_bfloat16*)tb;
            __nv_bfloat16* Alo = (__nv_bfloat16*)(tb + 18432);
            __nv_bfloat16* Bhi = (__nv_bfloat16*)(tb + 36864);
            __nv_bfloat16* Blo = (__nv_bfloat16*)(tb + 55296);
#pragma unroll
            for (int i = 0; i < 4; i++) {
                int o = tn[i] * LDT + tk[i];
                __nv_bfloat16 h0, h1, h2, h3, l0, l1, l2, l3;
                bf16_split(a4[i].x, h0, l0); bf16_split(a4[i].y, h1, l1);
                bf16_split(a4[i].z, h2, l2); bf16_split(a4[i].w, h3, l3);
                Ahi[o] = h0; Ahi[o + 1] = h1; Ahi[o + 2] = h2; Ahi[o + 3] = h3;
                Alo[o] = l0; Alo[o + 1] = l1; Alo[o + 2] = l2; Alo[o + 3] = l3;
                *(uint2*)&Bhi[o] = bhp[i];
                *(uint2*)&Blo[o] = blp[i];
            }
        }
        __syncthreads();
    }

#pragma unroll
    for (int t = 0; t < 4; t++)
        wmma::store_matrix_sync(Dov + m0 * 128 + nh * 64 + t * 16, facc[t], 128,
                                wmma::mem_row_major);
    __syncthreads();

    for (int p = tid; p < 16384; p += 512) {
        int n = p >> 7, v = p & 127;
        int gn = nb + n;
        if (gn < Nn) {
            float inv = 0.0625f / (g_dens[gn] + 1.f);  // 1/sqrt(256) / denom
            msg_out[(size_t)gn * 512 + (size_t)v * 4 + j] = Dov[n * 128 + v] * inv;
        }
    }
}

extern "C" void kernel_launch(void* const* d_in, const int* in_sizes, int n_in,
                              void* d_out, int out_size) {
    const float* na   = (const float*)d_in[0];
    const float* nf   = (const float*)d_in[1];
    const float* ea   = (const float*)d_in[2];
    const float* ef   = (const float*)d_in[3];
    const int*   eidx = (const int*)d_in[4];
    const float* Wup0 = (const float*)d_in[5];
    const float* Wup1 = (const float*)d_in[6];
    const float* R0   = (const float*)d_in[7];
    const float* R1   = (const float*)d_in[8];
    const float* R2   = (const float*)d_in[9];
    const float* R3   = (const float*)d_in[10];
    const float* Wd   = (const float*)d_in[11];
    const float* Wl0  = (const float*)d_in[12];
    const float* Wl1  = (const float*)d_in[13];
    const float* Wsk0 = (const float*)d_in[14];
    const float* Wsk1 = (const float*)d_in[15];
    float* out = (float*)d_out;
    float* msg_out = out;                       // message: (N,128,4)
    float* sc_out  = out + (size_t)Nn * 512;    // sc: (N,512)

    cudaFuncSetAttribute(node_up_kernel,   cudaFuncAttributeMaxDynamicSharedMemorySize, NU_SM_TOTAL);
    cudaFuncSetAttribute(node_skip_kernel, cudaFuncAttributeMaxDynamicSharedMemorySize, NK_SM_TOTAL);
    cudaFuncSetAttribute(edge_kernel, cudaFuncAttributeMaxDynamicSharedMemorySize, 110592);
    cudaFuncSetAttribute(lin_kernel,  cudaFuncAttributeMaxDynamicSharedMemorySize, LIN_SM_TOTAL);

    // Fork side stream FROM the capture-origin stream (capture-legal):
    cudaEventRecord(g_evF, 0);
    cudaStreamWaitEvent(g_s2, g_evF, 0);

    // side stream (low priority): clears -> prep_side -> node_skip
    clear_kernel<<<296, 256, 0, g_s2>>>();
    cudaEventRecord(g_evC, g_s2);
    prep_side_kernel<<<296, 256, 0, g_s2>>>(Wsk0, Wsk1, Wl0, Wl1);
    cudaEventRecord(g_evP, g_s2);
    node_skip_kernel<<<dim3(79, 4), 1024, NK_SM_TOTAL, g_s2>>>(nf, na, sc_out);
    cudaEventRecord(g_evB, g_s2);

    // main stream: prep_bup -> node_up -> (clears done) edge -> lin
    prep_bup_kernel<<<64, 256>>>(Wup0, Wup1);
    node_up_kernel<<<dim3(79, 4), 512, NU_SM_TOTAL>>>(nf);
    cudaStreamWaitEvent(0, g_evC, 0);   // edge needs g_M/g_dens cleared
    edge_kernel<<<1000, 512, 110592>>>(ef, ea, eidx, Wd, R0, R1, R2, R3);
    cudaStreamWaitEvent(0, g_evP, 0);   // lin needs g_Bln from prep_side
    lin_kernel<<<dim3(79, 4), 512, LIN_SM_TOTAL>>>(msg_out);
    cudaStreamWaitEvent(0, g_evB, 0);   // join skip before harness reads d_out
}